// round 12
// baseline (speedup 1.0000x reference)
#include <cuda_runtime.h>
#include <cuda_fp16.h>
#include <cstdint>

#define HIDDEN 1024
#define HEADS  16
#define HD     64
#define KP     256
#define BSZ    4
#define QLEN   4096
#define MR     (BSZ*QLEN)   // 16384

// ---------------- scratch (device globals) ----------------------------------
__device__ __half g_hs_h [MR*HIDDEN];
__device__ __half g_hs_th[(size_t)BSZ*HIDDEN*QLEN];
__device__ __half g_q_h  [MR*HIDDEN];
__device__ __half g_o_h  [MR*HIDDEN];
__device__ __half g_kp_h [BSZ*KP*HIDDEN];
__device__ __half g_vp_h [BSZ*KP*HIDDEN];
__device__ __half g_hE_h [BSZ*KP*HIDDEN];
__device__ __half g_hF_h [BSZ*KP*HIDDEN];
__device__ __half g_Et_h [KP*QLEN];
__device__ __half g_Ft_h [KP*QLEN];
__device__ __half g_Wq_h [HIDDEN*HIDDEN];
__device__ __half g_Wk_h [HIDDEN*HIDDEN];
__device__ __half g_Wv_h [HIDDEN*HIDDEN];
__device__ float  g_part [16 * KP * HIDDEN];   // 16MB scratch, reused twice
__device__ __half g_Wo_h [HIDDEN*HIDDEN];

// ============================== helpers =====================================
#define CP_ASYNC16(s, g) \
    asm volatile("cp.async.cg.shared.global [%0], [%1], 16;" :: "r"(s), "l"(g))
#define CP_ASYNC_COMMIT() asm volatile("cp.async.commit_group;")
#define CP_ASYNC_WAIT1()  asm volatile("cp.async.wait_group 1;" ::: "memory")
#define CP_ASYNC_WAIT0()  asm volatile("cp.async.wait_group 0;" ::: "memory")

__device__ __forceinline__ uint32_t smem_u32(const void* p) {
    uint32_t a;
    asm("{ .reg .u64 t; cvta.to.shared.u64 t, %1; cvt.u32.u64 %0, t; }"
        : "=r"(a) : "l"(p));
    return a;
}

#define MMA_F16(c, a0, a1, a2, a3, b0, b1)                                    \
    asm volatile("mma.sync.aligned.m16n8k16.row.col.f32.f16.f16.f32 "         \
        "{%0,%1,%2,%3}, {%4,%5,%6,%7}, {%8,%9}, {%0,%1,%2,%3};"               \
        : "+f"((c)[0]), "+f"((c)[1]), "+f"((c)[2]), "+f"((c)[3])              \
        : "r"(a0), "r"(a1), "r"(a2), "r"(a3), "r"(b0), "r"(b1))

#define LDSM4(d0, d1, d2, d3, a)                                              \
    asm volatile("ldmatrix.sync.aligned.m8n8.x4.shared.b16 {%0,%1,%2,%3}, [%4];" \
        : "=r"(d0), "=r"(d1), "=r"(d2), "=r"(d3) : "r"(a))

#define LDSM4T(d0, d1, d2, d3, a)                                             \
    asm volatile("ldmatrix.sync.aligned.m8n8.x4.trans.shared.b16 {%0,%1,%2,%3}, [%4];" \
        : "=r"(d0), "=r"(d1), "=r"(d2), "=r"(d3) : "r"(a))

// ---- GEMM tiling: BM=BN=128, BK=64 halves, 2-stage ---------------------------
#define ASTH 72
#define ABYT (128*ASTH*2)
#define STG  (2*ABYT)
#define SMEM_G (2*STG)                 // 73728 B

struct G { const __half* A; const __half* B; __half* Ch; float* Cf; };

__device__ __forceinline__ void stage_h64(const __half* P, int ldk,
                                          uint32_t sdst, int r0, int k0, int tid)
{
    #pragma unroll
    for (int i = 0; i < 4; i++) {
        int c = tid + i * 256;
        int row = c >> 3, kc = c & 7;
        CP_ASYNC16(sdst + row * 144 + kc * 16,
                   P + (size_t)(r0 + row) * ldk + k0 + kc * 8);
    }
}

// core mainloop (fragment double-buffering) + epilogue
__device__ __forceinline__ void gemm_core(
    const __half* A, const __half* B, __half* Ch, float* Cf,
    int N, int ldk, int kbase, int T, int m0, int n0)
{
    extern __shared__ char smem[];
    const int tid = threadIdx.x, lane = tid & 31, wid = tid >> 5;
    const int wm = (wid & 3) * 32, wn = (wid >> 2) * 64;
    const int gq = lane >> 2, r = lane & 3;
    const int lrow = lane & 15, lhi = (lane >> 4) * 8;
    const uint32_t sb = smem_u32(smem);
    const uint32_t aoff = ((wm + lrow) * ASTH + lhi) * 2;
    const uint32_t boff = ((wn + lrow) * ASTH + lhi) * 2;

    float cacc[2][8][4];
    #pragma unroll
    for (int i = 0; i < 2; i++)
        #pragma unroll
        for (int j = 0; j < 8; j++)
            #pragma unroll
            for (int q = 0; q < 4; q++) cacc[i][j][q] = 0.0f;

    stage_h64(A, ldk, sb,        m0, kbase, tid);
    stage_h64(B, ldk, sb + ABYT, n0, kbase, tid);
    CP_ASYNC_COMMIT();

    for (int t = 0; t < T; t++) {
        CP_ASYNC_WAIT0();
        __syncthreads();
        if (t + 1 < T) {
            uint32_t base = sb + ((t + 1) & 1) * STG;
            stage_h64(A, ldk, base,        m0, kbase + (t + 1) * 64, tid);
            stage_h64(B, ldk, base + ABYT, n0, kbase + (t + 1) * 64, tid);
            CP_ASYNC_COMMIT();
        }
        const uint32_t bA = sb + (t & 1) * STG;
        const uint32_t bB = bA + ABYT;

        uint32_t fa[2][8], fb[2][16];
        LDSM4(fa[0][0], fa[0][1], fa[0][2], fa[0][3], bA + aoff);
        LDSM4(fa[0][4], fa[0][5], fa[0][6], fa[0][7], bA + aoff + 16*ASTH*2);
        #pragma unroll
        for (int jj = 0; jj < 4; jj++)
            LDSM4(fb[0][4*jj], fb[0][4*jj+1], fb[0][4*jj+2], fb[0][4*jj+3],
                  bB + boff + jj*(16*ASTH*2));

        #pragma unroll
        for (int ks = 0; ks < 4; ks++) {
            const int cur = ks & 1, nxt = cur ^ 1;
            if (ks < 3) {
                LDSM4(fa[nxt][0], fa[nxt][1], fa[nxt][2], fa[nxt][3],
                      bA + aoff + (ks+1)*32);
                LDSM4(fa[nxt][4], fa[nxt][5], fa[nxt][6], fa[nxt][7],
                      bA + aoff + 16*ASTH*2 + (ks+1)*32);
                #pragma unroll
                for (int jj = 0; jj < 4; jj++)
                    LDSM4(fb[nxt][4*jj], fb[nxt][4*jj+1],
                          fb[nxt][4*jj+2], fb[nxt][4*jj+3],
                          bB + boff + jj*(16*ASTH*2) + (ks+1)*32);
            }
            #pragma unroll
            for (int jj = 0; jj < 4; jj++) {
                MMA_F16(cacc[0][2*jj],   fa[cur][0], fa[cur][1], fa[cur][2], fa[cur][3],
                        fb[cur][4*jj],   fb[cur][4*jj+2]);
                MMA_F16(cacc[0][2*jj+1], fa[cur][0], fa[cur][1], fa[cur][2], fa[cur][3],
                        fb[cur][4*jj+1], fb[cur][4*jj+3]);
                MMA_F16(cacc[1][2*jj],   fa[cur][4], fa[cur][5], fa[cur][6], fa[cur][7],
                        fb[cur][4*jj],   fb[cur][4*jj+2]);
                MMA_F16(cacc[1][2*jj+1], fa[cur][4], fa[cur][5], fa[cur][6], fa[cur][7],
                        fb[cur][4*jj+1], fb[cur][4*jj+3]);
            }
        }
    }

    #pragma unroll
    for (int i = 0; i < 2; i++) {
        int row = m0 + wm + i * 16 + gq;
        #pragma unroll
        for (int j = 0; j < 8; j++) {
            int col = n0 + wn + j * 8 + r * 2;
            if (Cf) {
                *(float2*)(Cf + (size_t)row * N + col) =
                    make_float2(cacc[i][j][0], cacc[i][j][1]);
                *(float2*)(Cf + (size_t)(row + 8) * N + col) =
                    make_float2(cacc[i][j][2], cacc[i][j][3]);
            } else {
                *(__half2*)(Ch + (size_t)row * N + col) =
                    __floats2half2_rn(cacc[i][j][0], cacc[i][j][1]);
                *(__half2*)(Ch + (size_t)(row + 8) * N + col) =
                    __floats2half2_rn(cacc[i][j][2], cacc[i][j][3]);
            }
        }
    }
}

// ============================================================================
// MEGA GEMM: bid<1024 -> q-projection; else split-K hE/hF partials.
// ============================================================================
__global__ __launch_bounds__(256, 2) void gemm_mega()
{
    const int bid = blockIdx.x;
    if (bid < 1024) {
        gemm_core(g_hs_h, g_Wq_h, g_q_h, nullptr,
                  HIDDEN, HIDDEN, 0, 16,
                  (bid >> 3) * 128, (bid & 7) * 128);
    } else {
        int s = bid - 1024;
        int v = s >> 4;
        int isF = v & 1, b = (v >> 1) & 3, ks = v >> 3;
        const __half* A = isF ? g_Ft_h : g_Et_h;
        const __half* B = g_hs_th + (size_t)b * HIDDEN * QLEN;
        float* Cf = g_part + (size_t)(ks * 8 + (v & 7)) * KP * HIDDEN;
        gemm_core(A, B, nullptr, Cf,
                  HIDDEN, QLEN, ks * 2048, 32,
                  ((s >> 3) & 1) * 128, (s & 7) * 128);
    }
}

// kp/vp split-K GEMM: grid (8, 8, 4); z: tensor = z&1, ks = z>>1.
// Partials -> g_part[z * 1Mfloat] (g_part free after reduce_hEF).
__global__ __launch_bounds__(256, 2) void gemm_kpvp()
{
    const int z = blockIdx.z;
    const int tensor = z & 1, ks = z >> 1;
    const __half* A = tensor ? g_hF_h : g_hE_h;
    const __half* B = tensor ? g_Wv_h : g_Wk_h;
    float* Cf = g_part + (size_t)z * (1024 * 1024);
    gemm_core(A, B, nullptr, Cf, HIDDEN, HIDDEN, ks * 512, 8,
              blockIdx.y * 128, blockIdx.x * 128);
}

// out-projection GEMM
__global__ __launch_bounds__(256, 2) void gemm_out(float* out)
{
    gemm_core(g_o_h, g_Wo_h, nullptr, out, HIDDEN, HIDDEN, 0, 16,
              blockIdx.y * 128, blockIdx.x * 128);
}

__global__ void reduce_hEF()
{
    int idx = blockIdx.x * 256 + threadIdx.x;
    int p = idx >> 16;
    int w4 = idx & 65535;
    const float4 x = ((const float4*)(g_part + (size_t)p       * KP*HIDDEN))[w4];
    const float4 y = ((const float4*)(g_part + (size_t)(8 + p) * KP*HIDDEN))[w4];
    int isF = p & 1, b = p >> 1;
    __half* dst = (isF ? g_hF_h : g_hE_h) + (size_t)b * KP * HIDDEN + w4 * 4;
    ((__half2*)dst)[0] = __floats2half2_rn(x.x + y.x, x.y + y.y);
    ((__half2*)dst)[1] = __floats2half2_rn(x.z + y.z, x.w + y.w);
}

__global__ void reduce_kpvp()
{
    int idx = blockIdx.x * 256 + threadIdx.x;   // 0..524287 float4 units
    int tensor = idx >> 18;                     // 262144 float4 per tensor
    int w4 = idx & 262143;
    const float4 x = ((const float4*)g_part)[(size_t)tensor * 262144 + w4];
    const float4 y = ((const float4*)g_part)[(size_t)(2 + tensor) * 262144 + w4];
    __half* dst = (tensor ? g_vp_h : g_kp_h) + (size_t)w4 * 4;
    ((__half2*)dst)[0] = __floats2half2_rn(x.x + y.x, x.y + y.y);
    ((__half2*)dst)[1] = __floats2half2_rn(x.z + y.z, x.w + y.w);
}

// ============================================================================
// fp16 mma attention: register P, h2exp2 softmax, pipelined K-fragment loads,
// ldmatrix.trans for V.
// ============================================================================
#define QST 72
#define KST 72
#define VST 72
#define QSO 0
#define KSO (128*QST)
#define VSO (KSO + 256*KST)
#define ATTN_SMEM ((VSO + 256*VST) * 2) // 92160 B

__global__ __launch_bounds__(256, 2) void attn_h()
{
    extern __shared__ __half smh[];

    const int tid  = threadIdx.x;
    const int lane = tid & 31;
    const int wid  = tid >> 5;
    const int gq   = lane >> 2, r = lane & 3;
    const int lrow = lane & 15, lhi = (lane >> 4) * 8;
    const int q0   = blockIdx.x << 7;
    const int h    = blockIdx.y;
    const int b    = blockIdx.z;

    const __half* qb  = g_q_h  + ((size_t)b*QLEN + q0) * HIDDEN + h*HD;
    const __half* kpb = g_kp_h + (size_t)b*KP*HIDDEN + h*HD;
    const __half* vpb = g_vp_h + (size_t)b*KP*HIDDEN + h*HD;
    const uint32_t sb = smem_u32(smh);

    // group A: Q + K'
    #pragma unroll
    for (int i = 0; i < 4; i++) {
        int c = tid + i * 256;
        int row = c >> 3, kc = c & 7;
        CP_ASYNC16(sb + (QSO + row * QST) * 2 + kc * 16,
                   qb + (size_t)row * HIDDEN + kc * 8);
    }
    #pragma unroll
    for (int i = 0; i < 8; i++) {
        int c = tid + i * 256;
        int row = c >> 3, kc = c & 7;
        CP_ASYNC16(sb + (KSO + row * KST) * 2 + kc * 16,
                   kpb + (size_t)row * HIDDEN + kc * 8);
    }
    CP_ASYNC_COMMIT();
    // group B: V' rows (key-major)
    #pragma unroll
    for (int i = 0; i < 8; i++) {
        int c = tid + i * 256;
        int row = c >> 3, kc = c & 7;
        CP_ASYNC16(sb + (VSO + row * VST) * 2 + kc * 16,
                   vpb + (size_t)row * HIDDEN + kc * 8);
    }
    CP_ASYNC_COMMIT();

    CP_ASYNC_WAIT1();
    __syncthreads();

    const int wm = wid * 16;
    const uint32_t qaoff = sb + ((QSO + (wm + lrow) * QST + lhi) * 2);
    uint32_t QA[4][4];
    #pragma unroll
    for (int ks = 0; ks < 4; ks++)
        LDSM4(QA[ks][0], QA[ks][1], QA[ks][2], QA[ks][3], qaoff + ks * 32);

    // scores -> exp2 fp16x2; K-fragments pipelined one step ahead
    const float KSC = 0.18033688f;
    const uint32_t kboff = sb + ((KSO + lrow * KST + lhi) * 2);
    uint32_t P[64];
    float sum0 = 0.0f, sum1 = 0.0f;

    uint32_t rbuf[2][4];
    LDSM4(rbuf[0][0], rbuf[0][1], rbuf[0][2], rbuf[0][3], kboff);   // (jp0,ks0)

    #pragma unroll
    for (int jp = 0; jp < 16; jp++) {
        float c0[4] = {0.f, 0.f, 0.f, 0.f};
        float c1[4] = {0.f, 0.f, 0.f, 0.f};
        #pragma unroll
        for (int ks = 0; ks < 4; ks++) {
            const int f = jp * 4 + ks;
            const int cur = f & 1, nxt = cur ^ 1;
            if (f < 63) {
                const int fn = f + 1;
                LDSM4(rbuf[nxt][0], rbuf[nxt][1], rbuf[nxt][2], rbuf[nxt][3],
                      kboff + (fn >> 2) * (16*KST*2) + (fn & 3) * 32);
            }
            MMA_F16(c0, QA[ks][0], QA[ks][1], QA[ks][2], QA[ks][3],
                    rbuf[cur][0], rbuf[cur][2]);
            MMA_F16(c1, QA[ks][0], QA[ks][1], QA[ks][2], QA[ks][3],
                    rbuf[cur][1], rbuf[cur][3]);
        }
        __half2 eA = h2exp2(__floats2half2_rn(c0[0]*KSC, c0[1]*KSC));
        __half2 eB = h2exp2(__floats2half2_rn(c0[2]*KSC, c0[3]*KSC));
        __half2 eC = h2exp2(__floats2half2_rn(c1[0]*KSC, c1[1]*KSC));
        __half2 eD = h2exp2(__floats2half2_rn(c1[2]*KSC, c1[3]*KSC));
        P[4*jp + 0] = *(uint32_t*)&eA;
        P[4*jp + 1] = *(uint32_t*)&eB;
        P[4*jp + 2] = *(uint32_t*)&eC;
        P[4*jp + 3] = *(uint32_t*)&eD;
        __half2 t0 = __hadd2(eA, eC);
        __half2 t1 = __hadd2(eB, eD);
        float2 f0 = __half22float2(t0); sum0 += f0.x + f0.y;
        float2 f1 = __half22float2(t1); sum1 += f1.x + f1.y;
    }

    sum0 += __shfl_xor_sync(0xffffffffu, sum0, 1);
    sum0 += __shfl_xor_sync(0xffffffffu, sum0, 2);
    sum1 += __shfl_xor_sync(0xffffffffu, sum1, 1);
    sum1 += __shfl_xor_sync(0xffffffffu, sum1, 2);
    const float ri0 = 1.0f / sum0, ri1 = 1.0f / sum1;

    CP_ASYNC_WAIT0();
    __syncthreads();

    // PV: A from P registers; B via ldmatrix.trans on V[key][d] tiles.
    float c2[8][4];
    #pragma unroll
    for (int j = 0; j < 8; j++)
        #pragma unroll
        for (int q = 0; q < 4; q++) c2[j][q] = 0.0f;

    #pragma unroll
    for (int t = 0; t < 16; t++) {
        #pragma unroll
        for (int g = 0; g < 4; g++) {
            uint32_t rb[4];
            LDSM4T(rb[0], rb[1], rb[2], rb[3],
                   sb + ((VSO + (t*16 + lrow) * VST + g*16 + lhi) * 2));
            MMA_F16(c2[2*g],   P[4*t+0], P[4*t+1], P[4*t+2], P[4*t+3], rb[0], rb[1]);
            MMA_F16(c2[2*g+1], P[4*t+0], P[4*t+1], P[4*t+2], P[4*t+3], rb[2], rb[3]);
        }
    }

    __half* ob = g_o_h + ((size_t)b*QLEN + q0 + wm) * HIDDEN + h*HD;
    #pragma unroll
    for (int j = 0; j < 8; j++) {
        int col = j * 8 + r * 2;
        *(__half2*)(ob + (size_t)gq * HIDDEN + col) =
            __floats2half2_rn(c2[j][0] * ri0, c2[j][1] * ri0);
        *(__half2*)(ob + (size_t)(gq + 8) * HIDDEN + col) =
            __floats2half2_rn(c2[j][2] * ri1, c2[j][3] * ri1);
    }
}

// ============================================================================
// Unified pre-pass: conv_hs (4096 blk, 64x64 tiles, half2 stores)
//                 | conv_w4 (4096 blk) | efh (1024 blk).  block (32, 8)
// ============================================================================
__global__ void prep(const float* __restrict__ hs,
                     const float* __restrict__ w0, const float* __restrict__ w1,
                     const float* __restrict__ w2, const float* __restrict__ w3,
                     const float* __restrict__ E,  const float* __restrict__ F)
{
    __shared__ float t[64][65];
    const int bid = blockIdx.x;
    const int tx = threadIdx.x, ty = threadIdx.y;

    if (bid < 4096) {               // ---- conv_hs: 64(s) x 64(n) tiles ------
        int x = bid & 63, y = (bid >> 6) & 15, b = bid >> 10;
        int s0 = x * 64, n0 = y * 64;
        #pragma unroll
        for (int i = 0; i < 8; i++) {
            int s = s0 + ty + i * 8;
            const float* src = hs + ((size_t)b * QLEN + s) * HIDDEN + n0;
            t[ty + i * 8][tx]      = src[tx];
            t[ty + i * 8][tx + 32] = src[tx + 32];
        }
        __syncthreads();
        #pragma unroll
        for (int i = 0; i < 8; i++) {           // hs_h: 64 rows x 32 half2
            int row = ty + i * 8;
            __half2 hv = __floats2half2_rn(t[row][2*tx], t[row][2*tx + 1]);
            *(__half2*)&g_hs_h[((size_t)b * QLEN + s0 + row) * HIDDEN + n0 + 2*tx] = hv;
        }
        #pragma unroll
        for (int i = 0; i < 8; i++) {           // hs_th: 64 n-rows x 32 half2(s)
            int n = ty + i * 8;
            __half2 hv = __floats2half2_rn(t[2*tx][n], t[2*tx + 1][n]);
            *(__half2*)&g_hs_th[((size_t)b * HIDDEN + n0 + n) * QLEN + s0 + 2*tx] = hv;
        }
    } else if (bid < 8192) {        // ---- conv_w4 ---------------------------
        int s = bid - 4096;
        int mat = s >> 10;
        const float* src = (mat == 0) ? w0 : (mat == 1) ? w1 : (mat == 2) ? w2 : w3;
        __half* dst = (mat == 0) ? g_Wq_h : (mat == 1) ? g_Wk_h
                    : (mat == 2) ? g_Wv_h : g_Wo_h;
        int i = (s & 1023) * 256 + ty * 32 + tx;
        float4 v = ((const float4*)src)[i];
        ((__half2*)dst)[i*2]   = __floats2half2_rn(v.x, v.y);
        ((__half2*)dst)[i*2+1] = __floats2half2_rn(v.z, v.w);
    } else {                        // ---- transpose_efh ---------------------
        int s = bid - 8192;
        int z = s >> 9, rem = s & 511;
        int x = rem & 63, y = rem >> 6;
        const float* src = z ? F : E;
        __half* dst = z ? g_Ft_h : g_Et_h;
        int s0 = x * 64, m0 = y * 32;
        #pragma unroll
        for (int i = 0; i < 8; i++)
            t[ty + i * 8][tx] = src[(size_t)(s0 + ty + i * 8) * KP + m0 + tx];
        __syncthreads();
        #pragma unroll
        for (int i = 0; i < 4; i++) {
            int m = m0 + ty + i * 8;
            __half2 hv = __floats2half2_rn(t[2*tx][ty + i * 8], t[2*tx + 1][ty + i * 8]);
            *(__half2*)&dst[(size_t)m * QLEN + s0 + 2*tx] = hv;
        }
    }
}

// ---------------------------------------------------------------------------
extern "C" void kernel_launch(void* const* d_in, const int* in_sizes, int n_in,
                              void* d_out, int out_size)
{
    const float* hs = (const float*)d_in[0];
    const float* Wq = (const float*)d_in[1];
    const float* Wk = (const float*)d_in[2];
    const float* Wv = (const float*)d_in[3];
    const float* Wo = (const float*)d_in[4];
    const float* E  = (const float*)d_in[5];
    const float* F  = (const float*)d_in[6];
    float* out = (float*)d_out;

    cudaFuncSetAttribute(gemm_mega, cudaFuncAttributeMaxDynamicSharedMemorySize, SMEM_G);
    cudaFuncSetAttribute(gemm_kpvp, cudaFuncAttributeMaxDynamicSharedMemorySize, SMEM_G);
    cudaFuncSetAttribute(gemm_out,  cudaFuncAttributeMaxDynamicSharedMemorySize, SMEM_G);
    cudaFuncSetAttribute(attn_h,    cudaFuncAttributeMaxDynamicSharedMemorySize, ATTN_SMEM);

    dim3 blk(256);

    // unified pre-pass
    prep<<<9216, dim3(32, 8)>>>(hs, Wq, Wk, Wv, Wo, E, F);

    // fused: q-projection + split-K hE/hF partials
    gemm_mega<<<1280, blk, SMEM_G>>>();
    reduce_hEF<<<2048, blk>>>();

    // kp/vp split-K GEMM + merge
    gemm_kpvp<<<dim3(8, 8, 4), blk, SMEM_G>>>();
    reduce_kpvp<<<2048, blk>>>();

    // attention
    attn_h<<<dim3(QLEN/128, HEADS, BSZ), blk, ATTN_SMEM>>>();

    // out = o @ Wo^T (fp32 to d_out)
    gemm_out<<<dim3(8, 128), blk, SMEM_G>>>(out);
}

// round 13
// speedup vs baseline: 1.0014x; 1.0014x over previous
#include <cuda_runtime.h>
#include <cuda_fp16.h>
#include <cstdint>

#define HIDDEN 1024
#define HEADS  16
#define HD     64
#define KP     256
#define BSZ    4
#define QLEN   4096
#define MR     (BSZ*QLEN)   // 16384

// ---------------- scratch (device globals) ----------------------------------
__device__ __half g_hs_h [MR*HIDDEN];
__device__ __half g_hs_th[(size_t)BSZ*HIDDEN*QLEN];
__device__ __half g_q_h  [MR*HIDDEN];
__device__ __half g_o_h  [MR*HIDDEN];
__device__ __half g_kp_h [BSZ*KP*HIDDEN];
__device__ __half g_vp_h [BSZ*KP*HIDDEN];
__device__ __half g_hE_h [BSZ*KP*HIDDEN];
__device__ __half g_hF_h [BSZ*KP*HIDDEN];
__device__ __half g_Et_h [KP*QLEN];
__device__ __half g_Ft_h [KP*QLEN];
__device__ __half g_Wq_h [HIDDEN*HIDDEN];
__device__ __half g_Wk_h [HIDDEN*HIDDEN];
__device__ __half g_Wv_h [HIDDEN*HIDDEN];
__device__ float  g_part [16 * KP * HIDDEN];   // 16MB scratch, reused twice
__device__ __half g_Wo_h [HIDDEN*HIDDEN];

// ============================== helpers =====================================
#define CP_ASYNC16(s, g) \
    asm volatile("cp.async.cg.shared.global [%0], [%1], 16;" :: "r"(s), "l"(g))
#define CP_ASYNC_COMMIT() asm volatile("cp.async.commit_group;")
#define CP_ASYNC_WAIT1()  asm volatile("cp.async.wait_group 1;" ::: "memory")
#define CP_ASYNC_WAIT0()  asm volatile("cp.async.wait_group 0;" ::: "memory")

__device__ __forceinline__ uint32_t smem_u32(const void* p) {
    uint32_t a;
    asm("{ .reg .u64 t; cvta.to.shared.u64 t, %1; cvt.u32.u64 %0, t; }"
        : "=r"(a) : "l"(p));
    return a;
}

#define MMA_F16(c, a0, a1, a2, a3, b0, b1)                                    \
    asm volatile("mma.sync.aligned.m16n8k16.row.col.f32.f16.f16.f32 "         \
        "{%0,%1,%2,%3}, {%4,%5,%6,%7}, {%8,%9}, {%0,%1,%2,%3};"               \
        : "+f"((c)[0]), "+f"((c)[1]), "+f"((c)[2]), "+f"((c)[3])              \
        : "r"(a0), "r"(a1), "r"(a2), "r"(a3), "r"(b0), "r"(b1))

// fp16-accumulator variant (rate-test): D,C fp16x2 pairs
#define MMA_F16A(c, a0, a1, a2, a3, b0, b1)                                   \
    asm volatile("mma.sync.aligned.m16n8k16.row.col.f16.f16.f16.f16 "         \
        "{%0,%1}, {%2,%3,%4,%5}, {%6,%7}, {%0,%1};"                           \
        : "+r"((c)[0]), "+r"((c)[1])                                          \
        : "r"(a0), "r"(a1), "r"(a2), "r"(a3), "r"(b0), "r"(b1))

#define LDSM4(d0, d1, d2, d3, a)                                              \
    asm volatile("ldmatrix.sync.aligned.m8n8.x4.shared.b16 {%0,%1,%2,%3}, [%4];" \
        : "=r"(d0), "=r"(d1), "=r"(d2), "=r"(d3) : "r"(a))

#define LDSM4T(d0, d1, d2, d3, a)                                             \
    asm volatile("ldmatrix.sync.aligned.m8n8.x4.trans.shared.b16 {%0,%1,%2,%3}, [%4];" \
        : "=r"(d0), "=r"(d1), "=r"(d2), "=r"(d3) : "r"(a))

// ---- GEMM tiling: BM=BN=128, BK=64 halves, 2-stage ---------------------------
#define ASTH 72
#define ABYT (128*ASTH*2)
#define STG  (2*ABYT)
#define SMEM_G (2*STG)                 // 73728 B

struct G { const __half* A; const __half* B; __half* Ch; float* Cf; };

__device__ __forceinline__ void stage_h64(const __half* P, int ldk,
                                          uint32_t sdst, int r0, int k0, int tid)
{
    #pragma unroll
    for (int i = 0; i < 4; i++) {
        int c = tid + i * 256;
        int row = c >> 3, kc = c & 7;
        CP_ASYNC16(sdst + row * 144 + kc * 16,
                   P + (size_t)(r0 + row) * ldk + k0 + kc * 8);
    }
}

// core mainloop (fragment double-buffering) + epilogue
__device__ __forceinline__ void gemm_core(
    const __half* A, const __half* B, __half* Ch, float* Cf,
    int N, int ldk, int kbase, int T, int m0, int n0)
{
    extern __shared__ char smem[];
    const int tid = threadIdx.x, lane = tid & 31, wid = tid >> 5;
    const int wm = (wid & 3) * 32, wn = (wid >> 2) * 64;
    const int gq = lane >> 2, r = lane & 3;
    const int lrow = lane & 15, lhi = (lane >> 4) * 8;
    const uint32_t sb = smem_u32(smem);
    const uint32_t aoff = ((wm + lrow) * ASTH + lhi) * 2;
    const uint32_t boff = ((wn + lrow) * ASTH + lhi) * 2;

    float cacc[2][8][4];
    #pragma unroll
    for (int i = 0; i < 2; i++)
        #pragma unroll
        for (int j = 0; j < 8; j++)
            #pragma unroll
            for (int q = 0; q < 4; q++) cacc[i][j][q] = 0.0f;

    stage_h64(A, ldk, sb,        m0, kbase, tid);
    stage_h64(B, ldk, sb + ABYT, n0, kbase, tid);
    CP_ASYNC_COMMIT();

    for (int t = 0; t < T; t++) {
        CP_ASYNC_WAIT0();
        __syncthreads();
        if (t + 1 < T) {
            uint32_t base = sb + ((t + 1) & 1) * STG;
            stage_h64(A, ldk, base,        m0, kbase + (t + 1) * 64, tid);
            stage_h64(B, ldk, base + ABYT, n0, kbase + (t + 1) * 64, tid);
            CP_ASYNC_COMMIT();
        }
        const uint32_t bA = sb + (t & 1) * STG;
        const uint32_t bB = bA + ABYT;

        uint32_t fa[2][8], fb[2][16];
        LDSM4(fa[0][0], fa[0][1], fa[0][2], fa[0][3], bA + aoff);
        LDSM4(fa[0][4], fa[0][5], fa[0][6], fa[0][7], bA + aoff + 16*ASTH*2);
        #pragma unroll
        for (int jj = 0; jj < 4; jj++)
            LDSM4(fb[0][4*jj], fb[0][4*jj+1], fb[0][4*jj+2], fb[0][4*jj+3],
                  bB + boff + jj*(16*ASTH*2));

        #pragma unroll
        for (int ks = 0; ks < 4; ks++) {
            const int cur = ks & 1, nxt = cur ^ 1;
            if (ks < 3) {
                LDSM4(fa[nxt][0], fa[nxt][1], fa[nxt][2], fa[nxt][3],
                      bA + aoff + (ks+1)*32);
                LDSM4(fa[nxt][4], fa[nxt][5], fa[nxt][6], fa[nxt][7],
                      bA + aoff + 16*ASTH*2 + (ks+1)*32);
                #pragma unroll
                for (int jj = 0; jj < 4; jj++)
                    LDSM4(fb[nxt][4*jj], fb[nxt][4*jj+1],
                          fb[nxt][4*jj+2], fb[nxt][4*jj+3],
                          bB + boff + jj*(16*ASTH*2) + (ks+1)*32);
            }
            #pragma unroll
            for (int jj = 0; jj < 4; jj++) {
                MMA_F16(cacc[0][2*jj],   fa[cur][0], fa[cur][1], fa[cur][2], fa[cur][3],
                        fb[cur][4*jj],   fb[cur][4*jj+2]);
                MMA_F16(cacc[0][2*jj+1], fa[cur][0], fa[cur][1], fa[cur][2], fa[cur][3],
                        fb[cur][4*jj+1], fb[cur][4*jj+3]);
                MMA_F16(cacc[1][2*jj],   fa[cur][4], fa[cur][5], fa[cur][6], fa[cur][7],
                        fb[cur][4*jj],   fb[cur][4*jj+2]);
                MMA_F16(cacc[1][2*jj+1], fa[cur][4], fa[cur][5], fa[cur][6], fa[cur][7],
                        fb[cur][4*jj+1], fb[cur][4*jj+3]);
            }
        }
    }

    #pragma unroll
    for (int i = 0; i < 2; i++) {
        int row = m0 + wm + i * 16 + gq;
        #pragma unroll
        for (int j = 0; j < 8; j++) {
            int col = n0 + wn + j * 8 + r * 2;
            if (Cf) {
                *(float2*)(Cf + (size_t)row * N + col) =
                    make_float2(cacc[i][j][0], cacc[i][j][1]);
                *(float2*)(Cf + (size_t)(row + 8) * N + col) =
                    make_float2(cacc[i][j][2], cacc[i][j][3]);
            } else {
                *(__half2*)(Ch + (size_t)row * N + col) =
                    __floats2half2_rn(cacc[i][j][0], cacc[i][j][1]);
                *(__half2*)(Ch + (size_t)(row + 8) * N + col) =
                    __floats2half2_rn(cacc[i][j][2], cacc[i][j][3]);
            }
        }
    }
}

// ============================================================================
// MEGA GEMM: bid<1024 -> q-projection; else split-K hE/hF partials.
// ============================================================================
__global__ __launch_bounds__(256, 2) void gemm_mega()
{
    const int bid = blockIdx.x;
    if (bid < 1024) {
        gemm_core(g_hs_h, g_Wq_h, g_q_h, nullptr,
                  HIDDEN, HIDDEN, 0, 16,
                  (bid >> 3) * 128, (bid & 7) * 128);
    } else {
        int s = bid - 1024;
        int v = s >> 4;
        int isF = v & 1, b = (v >> 1) & 3, ks = v >> 3;
        const __half* A = isF ? g_Ft_h : g_Et_h;
        const __half* B = g_hs_th + (size_t)b * HIDDEN * QLEN;
        float* Cf = g_part + (size_t)(ks * 8 + (v & 7)) * KP * HIDDEN;
        gemm_core(A, B, nullptr, Cf,
                  HIDDEN, QLEN, ks * 2048, 32,
                  ((s >> 3) & 1) * 128, (s & 7) * 128);
    }
}

// kp/vp split-K GEMM: grid (8, 8, 4); z: tensor = z&1, ks = z>>1.
__global__ __launch_bounds__(256, 2) void gemm_kpvp()
{
    const int z = blockIdx.z;
    const int tensor = z & 1, ks = z >> 1;
    const __half* A = tensor ? g_hF_h : g_hE_h;
    const __half* B = tensor ? g_Wv_h : g_Wk_h;
    float* Cf = g_part + (size_t)z * (1024 * 1024);
    gemm_core(A, B, nullptr, Cf, HIDDEN, HIDDEN, ks * 512, 8,
              blockIdx.y * 128, blockIdx.x * 128);
}

// out-projection GEMM
__global__ __launch_bounds__(256, 2) void gemm_out(float* out)
{
    gemm_core(g_o_h, g_Wo_h, nullptr, out, HIDDEN, HIDDEN, 0, 16,
              blockIdx.y * 128, blockIdx.x * 128);
}

__global__ void reduce_hEF()
{
    int idx = blockIdx.x * 256 + threadIdx.x;
    int p = idx >> 16;
    int w4 = idx & 65535;
    const float4 x = ((const float4*)(g_part + (size_t)p       * KP*HIDDEN))[w4];
    const float4 y = ((const float4*)(g_part + (size_t)(8 + p) * KP*HIDDEN))[w4];
    int isF = p & 1, b = p >> 1;
    __half* dst = (isF ? g_hF_h : g_hE_h) + (size_t)b * KP * HIDDEN + w4 * 4;
    ((__half2*)dst)[0] = __floats2half2_rn(x.x + y.x, x.y + y.y);
    ((__half2*)dst)[1] = __floats2half2_rn(x.z + y.z, x.w + y.w);
}

__global__ void reduce_kpvp()
{
    int idx = blockIdx.x * 256 + threadIdx.x;
    int tensor = idx >> 18;
    int w4 = idx & 262143;
    const float4 x = ((const float4*)g_part)[(size_t)tensor * 262144 + w4];
    const float4 y = ((const float4*)g_part)[(size_t)(2 + tensor) * 262144 + w4];
    __half* dst = (tensor ? g_vp_h : g_kp_h) + (size_t)w4 * 4;
    ((__half2*)dst)[0] = __floats2half2_rn(x.x + y.x, x.y + y.y);
    ((__half2*)dst)[1] = __floats2half2_rn(x.z + y.z, x.w + y.w);
}

// ============================================================================
// fp16 mma attention: scores fp32-acc, PV fp16-acc (rate experiment).
// ============================================================================
#define QST 72
#define KST 72
#define VST 72
#define QSO 0
#define KSO (128*QST)
#define VSO (KSO + 256*KST)
#define ATTN_SMEM ((VSO + 256*VST) * 2) // 92160 B

__global__ __launch_bounds__(256, 2) void attn_h()
{
    extern __shared__ __half smh[];

    const int tid  = threadIdx.x;
    const int lane = tid & 31;
    const int wid  = tid >> 5;
    const int gq   = lane >> 2, r = lane & 3;
    const int lrow = lane & 15, lhi = (lane >> 4) * 8;
    const int q0   = blockIdx.x << 7;
    const int h    = blockIdx.y;
    const int b    = blockIdx.z;

    const __half* qb  = g_q_h  + ((size_t)b*QLEN + q0) * HIDDEN + h*HD;
    const __half* kpb = g_kp_h + (size_t)b*KP*HIDDEN + h*HD;
    const __half* vpb = g_vp_h + (size_t)b*KP*HIDDEN + h*HD;
    const uint32_t sb = smem_u32(smh);

    // group A: Q + K'
    #pragma unroll
    for (int i = 0; i < 4; i++) {
        int c = tid + i * 256;
        int row = c >> 3, kc = c & 7;
        CP_ASYNC16(sb + (QSO + row * QST) * 2 + kc * 16,
                   qb + (size_t)row * HIDDEN + kc * 8);
    }
    #pragma unroll
    for (int i = 0; i < 8; i++) {
        int c = tid + i * 256;
        int row = c >> 3, kc = c & 7;
        CP_ASYNC16(sb + (KSO + row * KST) * 2 + kc * 16,
                   kpb + (size_t)row * HIDDEN + kc * 8);
    }
    CP_ASYNC_COMMIT();
    // group B: V' rows (key-major)
    #pragma unroll
    for (int i = 0; i < 8; i++) {
        int c = tid + i * 256;
        int row = c >> 3, kc = c & 7;
        CP_ASYNC16(sb + (VSO + row * VST) * 2 + kc * 16,
                   vpb + (size_t)row * HIDDEN + kc * 8);
    }
    CP_ASYNC_COMMIT();

    CP_ASYNC_WAIT1();
    __syncthreads();

    const int wm = wid * 16;
    const uint32_t qaoff = sb + ((QSO + (wm + lrow) * QST + lhi) * 2);
    uint32_t QA[4][4];
    #pragma unroll
    for (int ks = 0; ks < 4; ks++)
        LDSM4(QA[ks][0], QA[ks][1], QA[ks][2], QA[ks][3], qaoff + ks * 32);

    // scores -> exp2 fp16x2; K-fragments pipelined one step ahead
    const float KSC = 0.18033688f;
    const uint32_t kboff = sb + ((KSO + lrow * KST + lhi) * 2);
    uint32_t P[64];
    float sum0 = 0.0f, sum1 = 0.0f;

    uint32_t rbuf[2][4];
    LDSM4(rbuf[0][0], rbuf[0][1], rbuf[0][2], rbuf[0][3], kboff);

    #pragma unroll
    for (int jp = 0; jp < 16; jp++) {
        float c0[4] = {0.f, 0.f, 0.f, 0.f};
        float c1[4] = {0.f, 0.f, 0.f, 0.f};
        #pragma unroll
        for (int ks = 0; ks < 4; ks++) {
            const int f = jp * 4 + ks;
            const int cur = f & 1, nxt = cur ^ 1;
            if (f < 63) {
                const int fn = f + 1;
                LDSM4(rbuf[nxt][0], rbuf[nxt][1], rbuf[nxt][2], rbuf[nxt][3],
                      kboff + (fn >> 2) * (16*KST*2) + (fn & 3) * 32);
            }
            MMA_F16(c0, QA[ks][0], QA[ks][1], QA[ks][2], QA[ks][3],
                    rbuf[cur][0], rbuf[cur][2]);
            MMA_F16(c1, QA[ks][0], QA[ks][1], QA[ks][2], QA[ks][3],
                    rbuf[cur][1], rbuf[cur][3]);
        }
        __half2 eA = h2exp2(__floats2half2_rn(c0[0]*KSC, c0[1]*KSC));
        __half2 eB = h2exp2(__floats2half2_rn(c0[2]*KSC, c0[3]*KSC));
        __half2 eC = h2exp2(__floats2half2_rn(c1[0]*KSC, c1[1]*KSC));
        __half2 eD = h2exp2(__floats2half2_rn(c1[2]*KSC, c1[3]*KSC));
        P[4*jp + 0] = *(uint32_t*)&eA;
        P[4*jp + 1] = *(uint32_t*)&eB;
        P[4*jp + 2] = *(uint32_t*)&eC;
        P[4*jp + 3] = *(uint32_t*)&eD;
        __half2 t0 = __hadd2(eA, eC);
        __half2 t1 = __hadd2(eB, eD);
        float2 f0 = __half22float2(t0); sum0 += f0.x + f0.y;
        float2 f1 = __half22float2(t1); sum1 += f1.x + f1.y;
    }

    sum0 += __shfl_xor_sync(0xffffffffu, sum0, 1);
    sum0 += __shfl_xor_sync(0xffffffffu, sum0, 2);
    sum1 += __shfl_xor_sync(0xffffffffu, sum1, 1);
    sum1 += __shfl_xor_sync(0xffffffffu, sum1, 2);
    const float ri0 = 1.0f / sum0, ri1 = 1.0f / sum1;

    CP_ASYNC_WAIT0();
    __syncthreads();

    // PV: fp16 accumulators (rate test). c2h[j][0]=rows gq pair, [1]=rows gq+8.
    uint32_t c2h[8][2];
    #pragma unroll
    for (int j = 0; j < 8; j++) { c2h[j][0] = 0u; c2h[j][1] = 0u; }

    #pragma unroll
    for (int t = 0; t < 16; t++) {
        #pragma unroll
        for (int g = 0; g < 4; g++) {
            uint32_t rb[4];
            LDSM4T(rb[0], rb[1], rb[2], rb[3],
                   sb + ((VSO + (t*16 + lrow) * VST + g*16 + lhi) * 2));
            MMA_F16A(c2h[2*g],   P[4*t+0], P[4*t+1], P[4*t+2], P[4*t+3], rb[0], rb[1]);
            MMA_F16A(c2h[2*g+1], P[4*t+0], P[4*t+1], P[4*t+2], P[4*t+3], rb[2], rb[3]);
        }
    }

    __half* ob = g_o_h + ((size_t)b*QLEN + q0 + wm) * HIDDEN + h*HD;
    #pragma unroll
    for (int j = 0; j < 8; j++) {
        int col = j * 8 + r * 2;
        float2 lo = __half22float2(*(__half2*)&c2h[j][0]);
        float2 hi = __half22float2(*(__half2*)&c2h[j][1]);
        *(__half2*)(ob + (size_t)gq * HIDDEN + col) =
            __floats2half2_rn(lo.x * ri0, lo.y * ri0);
        *(__half2*)(ob + (size_t)(gq + 8) * HIDDEN + col) =
            __floats2half2_rn(hi.x * ri1, hi.y * ri1);
    }
}

// ============================================================================
// Unified pre-pass (unchanged from R12)
// ============================================================================
__global__ void prep(const float* __restrict__ hs,
                     const float* __restrict__ w0, const float* __restrict__ w1,
                     const float* __restrict__ w2, const float* __restrict__ w3,
                     const float* __restrict__ E,  const float* __restrict__ F)
{
    __shared__ float t[64][65];
    const int bid = blockIdx.x;
    const int tx = threadIdx.x, ty = threadIdx.y;

    if (bid < 4096) {               // ---- conv_hs: 64(s) x 64(n) tiles ------
        int x = bid & 63, y = (bid >> 6) & 15, b = bid >> 10;
        int s0 = x * 64, n0 = y * 64;
        #pragma unroll
        for (int i = 0; i < 8; i++) {
            int s = s0 + ty + i * 8;
            const float* src = hs + ((size_t)b * QLEN + s) * HIDDEN + n0;
            t[ty + i * 8][tx]      = src[tx];
            t[ty + i * 8][tx + 32] = src[tx + 32];
        }
        __syncthreads();
        #pragma unroll
        for (int i = 0; i < 8; i++) {
            int row = ty + i * 8;
            __half2 hv = __floats2half2_rn(t[row][2*tx], t[row][2*tx + 1]);
            *(__half2*)&g_hs_h[((size_t)b * QLEN + s0 + row) * HIDDEN + n0 + 2*tx] = hv;
        }
        #pragma unroll
        for (int i = 0; i < 8; i++) {
            int n = ty + i * 8;
            __half2 hv = __floats2half2_rn(t[2*tx][n], t[2*tx + 1][n]);
            *(__half2*)&g_hs_th[((size_t)b * HIDDEN + n0 + n) * QLEN + s0 + 2*tx] = hv;
        }
    } else if (bid < 8192) {        // ---- conv_w4 ---------------------------
        int s = bid - 4096;
        int mat = s >> 10;
        const float* src = (mat == 0) ? w0 : (mat == 1) ? w1 : (mat == 2) ? w2 : w3;
        __half* dst = (mat == 0) ? g_Wq_h : (mat == 1) ? g_Wk_h
                    : (mat == 2) ? g_Wv_h : g_Wo_h;
        int i = (s & 1023) * 256 + ty * 32 + tx;
        float4 v = ((const float4*)src)[i];
        ((__half2*)dst)[i*2]   = __floats2half2_rn(v.x, v.y);
        ((__half2*)dst)[i*2+1] = __floats2half2_rn(v.z, v.w);
    } else {                        // ---- transpose_efh ---------------------
        int s = bid - 8192;
        int z = s >> 9, rem = s & 511;
        int x = rem & 63, y = rem >> 6;
        const float* src = z ? F : E;
        __half* dst = z ? g_Ft_h : g_Et_h;
        int s0 = x * 64, m0 = y * 32;
        #pragma unroll
        for (int i = 0; i < 8; i++)
            t[ty + i * 8][tx] = src[(size_t)(s0 + ty + i * 8) * KP + m0 + tx];
        __syncthreads();
        #pragma unroll
        for (int i = 0; i < 4; i++) {
            int m = m0 + ty + i * 8;
            __half2 hv = __floats2half2_rn(t[2*tx][ty + i * 8], t[2*tx + 1][ty + i * 8]);
            *(__half2*)&dst[(size_t)m * QLEN + s0 + 2*tx] = hv;
        }
    }
}

// ---------------------------------------------------------------------------
extern "C" void kernel_launch(void* const* d_in, const int* in_sizes, int n_in,
                              void* d_out, int out_size)
{
    const float* hs = (const float*)d_in[0];
    const float* Wq = (const float*)d_in[1];
    const float* Wk = (const float*)d_in[2];
    const float* Wv = (const float*)d_in[3];
    const float* Wo = (const float*)d_in[4];
    const float* E  = (const float*)d_in[5];
    const float* F  = (const float*)d_in[6];
    float* out = (float*)d_out;

    cudaFuncSetAttribute(gemm_mega, cudaFuncAttributeMaxDynamicSharedMemorySize, SMEM_G);
    cudaFuncSetAttribute(gemm_kpvp, cudaFuncAttributeMaxDynamicSharedMemorySize, SMEM_G);
    cudaFuncSetAttribute(gemm_out,  cudaFuncAttributeMaxDynamicSharedMemorySize, SMEM_G);
    cudaFuncSetAttribute(attn_h,    cudaFuncAttributeMaxDynamicSharedMemorySize, ATTN_SMEM);

    dim3 blk(256);

    // unified pre-pass
    prep<<<9216, dim3(32, 8)>>>(hs, Wq, Wk, Wv, Wo, E, F);

    // fused: q-projection + split-K hE/hF partials
    gemm_mega<<<1280, blk, SMEM_G>>>();
    reduce_hEF<<<2048, blk>>>();

    // kp/vp split-K GEMM + merge
    gemm_kpvp<<<dim3(8, 8, 4), blk, SMEM_G>>>();
    reduce_kpvp<<<2048, blk>>>();

    // attention (PV fp16-acc)
    attn_h<<<dim3(QLEN/128, HEADS, BSZ), blk, ATTN_SMEM>>>();

    // out = o @ Wo^T (fp32 to d_out)
    gemm_out<<<dim3(8, 128), blk, SMEM_G>>>(out);
}

// round 14
// speedup vs baseline: 1.0144x; 1.0130x over previous
#include <cuda_runtime.h>
#include <cuda_fp16.h>
#include <cstdint>

#define HIDDEN 1024
#define HEADS  16
#define HD     64
#define KP     256
#define BSZ    4
#define QLEN   4096
#define MR     (BSZ*QLEN)   // 16384

// ---------------- scratch (device globals) ----------------------------------
__device__ __half g_hs_h [MR*HIDDEN];
__device__ __half g_hs_th[(size_t)BSZ*HIDDEN*QLEN];
__device__ __half g_q_h  [MR*HIDDEN];
__device__ __half g_o_h  [MR*HIDDEN];
__device__ __half g_kp_h [BSZ*KP*HIDDEN];
__device__ __half g_vp_h [BSZ*KP*HIDDEN];
__device__ __half g_hE_h [BSZ*KP*HIDDEN];
__device__ __half g_hF_h [BSZ*KP*HIDDEN];
__device__ __half g_Et_h [KP*QLEN];
__device__ __half g_Ft_h [KP*QLEN];
__device__ __half g_Wq_h [HIDDEN*HIDDEN];
__device__ __half g_Wk_h [HIDDEN*HIDDEN];
__device__ __half g_Wv_h [HIDDEN*HIDDEN];
__device__ float  g_part [16 * KP * HIDDEN];   // split-K partials for hE/hF
__device__ __half g_Wo_h [HIDDEN*HIDDEN];

// ============================== helpers =====================================
#define CP_ASYNC16(s, g) \
    asm volatile("cp.async.cg.shared.global [%0], [%1], 16;" :: "r"(s), "l"(g))
#define CP_ASYNC_COMMIT() asm volatile("cp.async.commit_group;")
#define CP_ASYNC_WAIT1()  asm volatile("cp.async.wait_group 1;" ::: "memory")
#define CP_ASYNC_WAIT0()  asm volatile("cp.async.wait_group 0;" ::: "memory")

__device__ __forceinline__ uint32_t smem_u32(const void* p) {
    uint32_t a;
    asm("{ .reg .u64 t; cvta.to.shared.u64 t, %1; cvt.u32.u64 %0, t; }"
        : "=r"(a) : "l"(p));
    return a;
}

#define MMA_F16(c, a0, a1, a2, a3, b0, b1)                                    \
    asm volatile("mma.sync.aligned.m16n8k16.row.col.f32.f16.f16.f32 "         \
        "{%0,%1,%2,%3}, {%4,%5,%6,%7}, {%8,%9}, {%0,%1,%2,%3};"               \
        : "+f"((c)[0]), "+f"((c)[1]), "+f"((c)[2]), "+f"((c)[3])              \
        : "r"(a0), "r"(a1), "r"(a2), "r"(a3), "r"(b0), "r"(b1))

#define LDSM4(d0, d1, d2, d3, a)                                              \
    asm volatile("ldmatrix.sync.aligned.m8n8.x4.shared.b16 {%0,%1,%2,%3}, [%4];" \
        : "=r"(d0), "=r"(d1), "=r"(d2), "=r"(d3) : "r"(a))

#define LDSM4T(d0, d1, d2, d3, a)                                             \
    asm volatile("ldmatrix.sync.aligned.m8n8.x4.trans.shared.b16 {%0,%1,%2,%3}, [%4];" \
        : "=r"(d0), "=r"(d1), "=r"(d2), "=r"(d3) : "r"(a))

// ---- GEMM tiling: BM=BN=128, BK=64 halves, 2-stage ---------------------------
#define ASTH 72
#define ABYT (128*ASTH*2)
#define STG  (2*ABYT)
#define SMEM_G (2*STG)                 // 73728 B

struct G { const __half* A; const __half* B; __half* Ch; float* Cf; };

__device__ __forceinline__ void stage_h64(const __half* P, int ldk,
                                          uint32_t sdst, int r0, int k0, int tid)
{
    #pragma unroll
    for (int i = 0; i < 4; i++) {
        int c = tid + i * 256;
        int row = c >> 3, kc = c & 7;
        CP_ASYNC16(sdst + row * 144 + kc * 16,
                   P + (size_t)(r0 + row) * ldk + k0 + kc * 8);
    }
}

// core mainloop (fragment double-buffering) + epilogue
__device__ __forceinline__ void gemm_core(
    const __half* A, const __half* B, __half* Ch, float* Cf,
    int N, int ldk, int kbase, int T, int m0, int n0)
{
    extern __shared__ char smem[];
    const int tid = threadIdx.x, lane = tid & 31, wid = tid >> 5;
    const int wm = (wid & 3) * 32, wn = (wid >> 2) * 64;
    const int gq = lane >> 2, r = lane & 3;
    const int lrow = lane & 15, lhi = (lane >> 4) * 8;
    const uint32_t sb = smem_u32(smem);
    const uint32_t aoff = ((wm + lrow) * ASTH + lhi) * 2;
    const uint32_t boff = ((wn + lrow) * ASTH + lhi) * 2;

    float cacc[2][8][4];
    #pragma unroll
    for (int i = 0; i < 2; i++)
        #pragma unroll
        for (int j = 0; j < 8; j++)
            #pragma unroll
            for (int q = 0; q < 4; q++) cacc[i][j][q] = 0.0f;

    stage_h64(A, ldk, sb,        m0, kbase, tid);
    stage_h64(B, ldk, sb + ABYT, n0, kbase, tid);
    CP_ASYNC_COMMIT();

    for (int t = 0; t < T; t++) {
        CP_ASYNC_WAIT0();
        __syncthreads();
        if (t + 1 < T) {
            uint32_t base = sb + ((t + 1) & 1) * STG;
            stage_h64(A, ldk, base,        m0, kbase + (t + 1) * 64, tid);
            stage_h64(B, ldk, base + ABYT, n0, kbase + (t + 1) * 64, tid);
            CP_ASYNC_COMMIT();
        }
        const uint32_t bA = sb + (t & 1) * STG;
        const uint32_t bB = bA + ABYT;

        uint32_t fa[2][8], fb[2][16];
        LDSM4(fa[0][0], fa[0][1], fa[0][2], fa[0][3], bA + aoff);
        LDSM4(fa[0][4], fa[0][5], fa[0][6], fa[0][7], bA + aoff + 16*ASTH*2);
        #pragma unroll
        for (int jj = 0; jj < 4; jj++)
            LDSM4(fb[0][4*jj], fb[0][4*jj+1], fb[0][4*jj+2], fb[0][4*jj+3],
                  bB + boff + jj*(16*ASTH*2));

        #pragma unroll
        for (int ks = 0; ks < 4; ks++) {
            const int cur = ks & 1, nxt = cur ^ 1;
            if (ks < 3) {
                LDSM4(fa[nxt][0], fa[nxt][1], fa[nxt][2], fa[nxt][3],
                      bA + aoff + (ks+1)*32);
                LDSM4(fa[nxt][4], fa[nxt][5], fa[nxt][6], fa[nxt][7],
                      bA + aoff + 16*ASTH*2 + (ks+1)*32);
                #pragma unroll
                for (int jj = 0; jj < 4; jj++)
                    LDSM4(fb[nxt][4*jj], fb[nxt][4*jj+1],
                          fb[nxt][4*jj+2], fb[nxt][4*jj+3],
                          bB + boff + jj*(16*ASTH*2) + (ks+1)*32);
            }
            #pragma unroll
            for (int jj = 0; jj < 4; jj++) {
                MMA_F16(cacc[0][2*jj],   fa[cur][0], fa[cur][1], fa[cur][2], fa[cur][3],
                        fb[cur][4*jj],   fb[cur][4*jj+2]);
                MMA_F16(cacc[0][2*jj+1], fa[cur][0], fa[cur][1], fa[cur][2], fa[cur][3],
                        fb[cur][4*jj+1], fb[cur][4*jj+3]);
                MMA_F16(cacc[1][2*jj],   fa[cur][4], fa[cur][5], fa[cur][6], fa[cur][7],
                        fb[cur][4*jj],   fb[cur][4*jj+2]);
                MMA_F16(cacc[1][2*jj+1], fa[cur][4], fa[cur][5], fa[cur][6], fa[cur][7],
                        fb[cur][4*jj+1], fb[cur][4*jj+3]);
            }
        }
    }

    #pragma unroll
    for (int i = 0; i < 2; i++) {
        int row = m0 + wm + i * 16 + gq;
        #pragma unroll
        for (int j = 0; j < 8; j++) {
            int col = n0 + wn + j * 8 + r * 2;
            if (Cf) {
                *(float2*)(Cf + (size_t)row * N + col) =
                    make_float2(cacc[i][j][0], cacc[i][j][1]);
                *(float2*)(Cf + (size_t)(row + 8) * N + col) =
                    make_float2(cacc[i][j][2], cacc[i][j][3]);
            } else {
                *(__half2*)(Ch + (size_t)row * N + col) =
                    __floats2half2_rn(cacc[i][j][0], cacc[i][j][1]);
                *(__half2*)(Ch + (size_t)(row + 8) * N + col) =
                    __floats2half2_rn(cacc[i][j][2], cacc[i][j][3]);
            }
        }
    }
}

// ============================================================================
// MEGA GEMM: bid<256 -> long split-K hE/hF partials (scheduled first);
//            bid>=256 -> q-projection.
// ============================================================================
__global__ __launch_bounds__(256, 2) void gemm_mega()
{
    const int bid = blockIdx.x;
    if (bid < 256) {
        int v = bid >> 4;
        int isF = v & 1, b = (v >> 1) & 3, ks = v >> 3;
        const __half* A = isF ? g_Ft_h : g_Et_h;
        const __half* B = g_hs_th + (size_t)b * HIDDEN * QLEN;
        float* Cf = g_part + (size_t)(ks * 8 + (v & 7)) * KP * HIDDEN;
        gemm_core(A, B, nullptr, Cf,
                  HIDDEN, QLEN, ks * 2048, 32,
                  ((bid >> 3) & 1) * 128, (bid & 7) * 128);
    } else {
        int s = bid - 256;
        gemm_core(g_hs_h, g_Wq_h, g_q_h, nullptr,
                  HIDDEN, HIDDEN, 0, 16,
                  (s >> 3) * 128, (s & 7) * 128);
    }
}

// kp/vp GEMM: non-split (R11-proven faster than split-K + reduce).
// grid (8, 8, 2): z picks kp vs vp.
__global__ __launch_bounds__(256, 2) void gemm_kpvp()
{
    const int tensor = blockIdx.z;
    const __half* A = tensor ? g_hF_h : g_hE_h;
    const __half* B = tensor ? g_Wv_h : g_Wk_h;
    __half* Ch = tensor ? g_vp_h : g_kp_h;
    gemm_core(A, B, Ch, nullptr, HIDDEN, HIDDEN, 0, 16,
              blockIdx.y * 128, blockIdx.x * 128);
}

// out-projection GEMM
__global__ __launch_bounds__(256, 2) void gemm_out(float* out)
{
    gemm_core(g_o_h, g_Wo_h, nullptr, out, HIDDEN, HIDDEN, 0, 16,
              blockIdx.y * 128, blockIdx.x * 128);
}

__global__ void reduce_hEF()
{
    int idx = blockIdx.x * 256 + threadIdx.x;
    int p = idx >> 16;
    int w4 = idx & 65535;
    const float4 x = ((const float4*)(g_part + (size_t)p       * KP*HIDDEN))[w4];
    const float4 y = ((const float4*)(g_part + (size_t)(8 + p) * KP*HIDDEN))[w4];
    int isF = p & 1, b = p >> 1;
    __half* dst = (isF ? g_hF_h : g_hE_h) + (size_t)b * KP * HIDDEN + w4 * 4;
    ((__half2*)dst)[0] = __floats2half2_rn(x.x + y.x, x.y + y.y);
    ((__half2*)dst)[1] = __floats2half2_rn(x.z + y.z, x.w + y.w);
}

// ============================================================================
// fp16 mma attention: scores fp32-acc, PV fp32-acc (reverted), register P,
// h2exp2 softmax, pipelined K-fragments, ldmatrix.trans for V.
// ============================================================================
#define QST 72
#define KST 72
#define VST 72
#define QSO 0
#define KSO (128*QST)
#define VSO (KSO + 256*KST)
#define ATTN_SMEM ((VSO + 256*VST) * 2) // 92160 B

__global__ __launch_bounds__(256, 2) void attn_h()
{
    extern __shared__ __half smh[];

    const int tid  = threadIdx.x;
    const int lane = tid & 31;
    const int wid  = tid >> 5;
    const int gq   = lane >> 2, r = lane & 3;
    const int lrow = lane & 15, lhi = (lane >> 4) * 8;
    const int q0   = blockIdx.x << 7;
    const int h    = blockIdx.y;
    const int b    = blockIdx.z;

    const __half* qb  = g_q_h  + ((size_t)b*QLEN + q0) * HIDDEN + h*HD;
    const __half* kpb = g_kp_h + (size_t)b*KP*HIDDEN + h*HD;
    const __half* vpb = g_vp_h + (size_t)b*KP*HIDDEN + h*HD;
    const uint32_t sb = smem_u32(smh);

    // group A: Q + K'
    #pragma unroll
    for (int i = 0; i < 4; i++) {
        int c = tid + i * 256;
        int row = c >> 3, kc = c & 7;
        CP_ASYNC16(sb + (QSO + row * QST) * 2 + kc * 16,
                   qb + (size_t)row * HIDDEN + kc * 8);
    }
    #pragma unroll
    for (int i = 0; i < 8; i++) {
        int c = tid + i * 256;
        int row = c >> 3, kc = c & 7;
        CP_ASYNC16(sb + (KSO + row * KST) * 2 + kc * 16,
                   kpb + (size_t)row * HIDDEN + kc * 8);
    }
    CP_ASYNC_COMMIT();
    // group B: V' rows (key-major)
    #pragma unroll
    for (int i = 0; i < 8; i++) {
        int c = tid + i * 256;
        int row = c >> 3, kc = c & 7;
        CP_ASYNC16(sb + (VSO + row * VST) * 2 + kc * 16,
                   vpb + (size_t)row * HIDDEN + kc * 8);
    }
    CP_ASYNC_COMMIT();

    CP_ASYNC_WAIT1();
    __syncthreads();

    const int wm = wid * 16;
    const uint32_t qaoff = sb + ((QSO + (wm + lrow) * QST + lhi) * 2);
    uint32_t QA[4][4];
    #pragma unroll
    for (int ks = 0; ks < 4; ks++)
        LDSM4(QA[ks][0], QA[ks][1], QA[ks][2], QA[ks][3], qaoff + ks * 32);

    const float KSC = 0.18033688f;
    const uint32_t kboff = sb + ((KSO + lrow * KST + lhi) * 2);
    uint32_t P[64];
    float sum0 = 0.0f, sum1 = 0.0f;

    uint32_t rbuf[2][4];
    LDSM4(rbuf[0][0], rbuf[0][1], rbuf[0][2], rbuf[0][3], kboff);

    #pragma unroll
    for (int jp = 0; jp < 16; jp++) {
        float c0[4] = {0.f, 0.f, 0.f, 0.f};
        float c1[4] = {0.f, 0.f, 0.f, 0.f};
        #pragma unroll
        for (int ks = 0; ks < 4; ks++) {
            const int f = jp * 4 + ks;
            const int cur = f & 1, nxt = cur ^ 1;
            if (f < 63) {
                const int fn = f + 1;
                LDSM4(rbuf[nxt][0], rbuf[nxt][1], rbuf[nxt][2], rbuf[nxt][3],
                      kboff + (fn >> 2) * (16*KST*2) + (fn & 3) * 32);
            }
            MMA_F16(c0, QA[ks][0], QA[ks][1], QA[ks][2], QA[ks][3],
                    rbuf[cur][0], rbuf[cur][2]);
            MMA_F16(c1, QA[ks][0], QA[ks][1], QA[ks][2], QA[ks][3],
                    rbuf[cur][1], rbuf[cur][3]);
        }
        __half2 eA = h2exp2(__floats2half2_rn(c0[0]*KSC, c0[1]*KSC));
        __half2 eB = h2exp2(__floats2half2_rn(c0[2]*KSC, c0[3]*KSC));
        __half2 eC = h2exp2(__floats2half2_rn(c1[0]*KSC, c1[1]*KSC));
        __half2 eD = h2exp2(__floats2half2_rn(c1[2]*KSC, c1[3]*KSC));
        P[4*jp + 0] = *(uint32_t*)&eA;
        P[4*jp + 1] = *(uint32_t*)&eB;
        P[4*jp + 2] = *(uint32_t*)&eC;
        P[4*jp + 3] = *(uint32_t*)&eD;
        __half2 t0 = __hadd2(eA, eC);
        __half2 t1 = __hadd2(eB, eD);
        float2 f0 = __half22float2(t0); sum0 += f0.x + f0.y;
        float2 f1 = __half22float2(t1); sum1 += f1.x + f1.y;
    }

    sum0 += __shfl_xor_sync(0xffffffffu, sum0, 1);
    sum0 += __shfl_xor_sync(0xffffffffu, sum0, 2);
    sum1 += __shfl_xor_sync(0xffffffffu, sum1, 1);
    sum1 += __shfl_xor_sync(0xffffffffu, sum1, 2);
    const float ri0 = 1.0f / sum0, ri1 = 1.0f / sum1;

    CP_ASYNC_WAIT0();
    __syncthreads();

    // PV: fp32 accumulators; B via ldmatrix.trans on V[key][d] tiles.
    float c2[8][4];
    #pragma unroll
    for (int j = 0; j < 8; j++)
        #pragma unroll
        for (int q = 0; q < 4; q++) c2[j][q] = 0.0f;

    #pragma unroll
    for (int t = 0; t < 16; t++) {
        #pragma unroll
        for (int g = 0; g < 4; g++) {
            uint32_t rb[4];
            LDSM4T(rb[0], rb[1], rb[2], rb[3],
                   sb + ((VSO + (t*16 + lrow) * VST + g*16 + lhi) * 2));
            MMA_F16(c2[2*g],   P[4*t+0], P[4*t+1], P[4*t+2], P[4*t+3], rb[0], rb[1]);
            MMA_F16(c2[2*g+1], P[4*t+0], P[4*t+1], P[4*t+2], P[4*t+3], rb[2], rb[3]);
        }
    }

    __half* ob = g_o_h + ((size_t)b*QLEN + q0 + wm) * HIDDEN + h*HD;
    #pragma unroll
    for (int j = 0; j < 8; j++) {
        int col = j * 8 + r * 2;
        *(__half2*)(ob + (size_t)gq * HIDDEN + col) =
            __floats2half2_rn(c2[j][0] * ri0, c2[j][1] * ri0);
        *(__half2*)(ob + (size_t)(gq + 8) * HIDDEN + col) =
            __floats2half2_rn(c2[j][2] * ri1, c2[j][3] * ri1);
    }
}

// ============================================================================
// Unified pre-pass (unchanged)
// ============================================================================
__global__ void prep(const float* __restrict__ hs,
                     const float* __restrict__ w0, const float* __restrict__ w1,
                     const float* __restrict__ w2, const float* __restrict__ w3,
                     const float* __restrict__ E,  const float* __restrict__ F)
{
    __shared__ float t[64][65];
    const int bid = blockIdx.x;
    const int tx = threadIdx.x, ty = threadIdx.y;

    if (bid < 4096) {               // ---- conv_hs: 64(s) x 64(n) tiles ------
        int x = bid & 63, y = (bid >> 6) & 15, b = bid >> 10;
        int s0 = x * 64, n0 = y * 64;
        #pragma unroll
        for (int i = 0; i < 8; i++) {
            int s = s0 + ty + i * 8;
            const float* src = hs + ((size_t)b * QLEN + s) * HIDDEN + n0;
            t[ty + i * 8][tx]      = src[tx];
            t[ty + i * 8][tx + 32] = src[tx + 32];
        }
        __syncthreads();
        #pragma unroll
        for (int i = 0; i < 8; i++) {
            int row = ty + i * 8;
            __half2 hv = __floats2half2_rn(t[row][2*tx], t[row][2*tx + 1]);
            *(__half2*)&g_hs_h[((size_t)b * QLEN + s0 + row) * HIDDEN + n0 + 2*tx] = hv;
        }
        #pragma unroll
        for (int i = 0; i < 8; i++) {
            int n = ty + i * 8;
            __half2 hv = __floats2half2_rn(t[2*tx][n], t[2*tx + 1][n]);
            *(__half2*)&g_hs_th[((size_t)b * HIDDEN + n0 + n) * QLEN + s0 + 2*tx] = hv;
        }
    } else if (bid < 8192) {        // ---- conv_w4 ---------------------------
        int s = bid - 4096;
        int mat = s >> 10;
        const float* src = (mat == 0) ? w0 : (mat == 1) ? w1 : (mat == 2) ? w2 : w3;
        __half* dst = (mat == 0) ? g_Wq_h : (mat == 1) ? g_Wk_h
                    : (mat == 2) ? g_Wv_h : g_Wo_h;
        int i = (s & 1023) * 256 + ty * 32 + tx;
        float4 v = ((const float4*)src)[i];
        ((__half2*)dst)[i*2]   = __floats2half2_rn(v.x, v.y);
        ((__half2*)dst)[i*2+1] = __floats2half2_rn(v.z, v.w);
    } else {                        // ---- transpose_efh ---------------------
        int s = bid - 8192;
        int z = s >> 9, rem = s & 511;
        int x = rem & 63, y = rem >> 6;
        const float* src = z ? F : E;
        __half* dst = z ? g_Ft_h : g_Et_h;
        int s0 = x * 64, m0 = y * 32;
        #pragma unroll
        for (int i = 0; i < 8; i++)
            t[ty + i * 8][tx] = src[(size_t)(s0 + ty + i * 8) * KP + m0 + tx];
        __syncthreads();
        #pragma unroll
        for (int i = 0; i < 4; i++) {
            int m = m0 + ty + i * 8;
            __half2 hv = __floats2half2_rn(t[2*tx][ty + i * 8], t[2*tx + 1][ty + i * 8]);
            *(__half2*)&dst[(size_t)m * QLEN + s0 + 2*tx] = hv;
        }
    }
}

// ---------------------------------------------------------------------------
extern "C" void kernel_launch(void* const* d_in, const int* in_sizes, int n_in,
                              void* d_out, int out_size)
{
    const float* hs = (const float*)d_in[0];
    const float* Wq = (const float*)d_in[1];
    const float* Wk = (const float*)d_in[2];
    const float* Wv = (const float*)d_in[3];
    const float* Wo = (const float*)d_in[4];
    const float* E  = (const float*)d_in[5];
    const float* F  = (const float*)d_in[6];
    float* out = (float*)d_out;

    cudaFuncSetAttribute(gemm_mega, cudaFuncAttributeMaxDynamicSharedMemorySize, SMEM_G);
    cudaFuncSetAttribute(gemm_kpvp, cudaFuncAttributeMaxDynamicSharedMemorySize, SMEM_G);
    cudaFuncSetAttribute(gemm_out,  cudaFuncAttributeMaxDynamicSharedMemorySize, SMEM_G);
    cudaFuncSetAttribute(attn_h,    cudaFuncAttributeMaxDynamicSharedMemorySize, ATTN_SMEM);

    dim3 blk(256);

    // unified pre-pass
    prep<<<9216, dim3(32, 8)>>>(hs, Wq, Wk, Wv, Wo, E, F);

    // fused: split-K hE/hF partials (first, long) + q-projection
    gemm_mega<<<1280, blk, SMEM_G>>>();
    reduce_hEF<<<2048, blk>>>();

    // kp/vp GEMM (non-split, direct fp16 output)
    gemm_kpvp<<<dim3(8, 8, 2), blk, SMEM_G>>>();

    // attention
    attn_h<<<dim3(QLEN/128, HEADS, BSZ), blk, ATTN_SMEM>>>();

    // out = o @ Wo^T (fp32 to d_out)
    gemm_out<<<dim3(8, 128), blk, SMEM_G>>>(out);
}

// round 15
// speedup vs baseline: 1.0810x; 1.0656x over previous
#include <cuda_runtime.h>
#include <cuda_fp16.h>
#include <cstdint>

#define HIDDEN 1024
#define HEADS  16
#define HD     64
#define KP     256
#define BSZ    4
#define QLEN   4096
#define MR     (BSZ*QLEN)   // 16384

// ---------------- scratch (device globals) ----------------------------------
__device__ __half g_hs_h [MR*HIDDEN];
__device__ __half g_hs_th[(size_t)BSZ*HIDDEN*QLEN];
__device__ __half g_q_h  [MR*HIDDEN];
__device__ __half g_o_h  [MR*HIDDEN];
__device__ __half g_kp_h [BSZ*KP*HIDDEN];
__device__ __half g_vp_h [BSZ*KP*HIDDEN];
__device__ __half g_hE_h [BSZ*KP*HIDDEN];
__device__ __half g_hF_h [BSZ*KP*HIDDEN];
__device__ __half g_Et_h [KP*QLEN];
__device__ __half g_Ft_h [KP*QLEN];
__device__ __half g_Wq_h [HIDDEN*HIDDEN];
__device__ __half g_Wk_h [HIDDEN*HIDDEN];
__device__ __half g_Wv_h [HIDDEN*HIDDEN];
__device__ __half g_Wo_h [HIDDEN*HIDDEN];
__device__ int    g_done;               // EF completion counter (reset in prep)

// ============================== helpers =====================================
#define CP_ASYNC16(s, g) \
    asm volatile("cp.async.cg.shared.global [%0], [%1], 16;" :: "r"(s), "l"(g))
#define CP_ASYNC_COMMIT() asm volatile("cp.async.commit_group;")
#define CP_ASYNC_WAIT1()  asm volatile("cp.async.wait_group 1;" ::: "memory")
#define CP_ASYNC_WAIT0()  asm volatile("cp.async.wait_group 0;" ::: "memory")

__device__ __forceinline__ uint32_t smem_u32(const void* p) {
    uint32_t a;
    asm("{ .reg .u64 t; cvta.to.shared.u64 t, %1; cvt.u32.u64 %0, t; }"
        : "=r"(a) : "l"(p));
    return a;
}

#define MMA_F16(c, a0, a1, a2, a3, b0, b1)                                    \
    asm volatile("mma.sync.aligned.m16n8k16.row.col.f32.f16.f16.f32 "         \
        "{%0,%1,%2,%3}, {%4,%5,%6,%7}, {%8,%9}, {%0,%1,%2,%3};"               \
        : "+f"((c)[0]), "+f"((c)[1]), "+f"((c)[2]), "+f"((c)[3])              \
        : "r"(a0), "r"(a1), "r"(a2), "r"(a3), "r"(b0), "r"(b1))

#define LDSM4(d0, d1, d2, d3, a)                                              \
    asm volatile("ldmatrix.sync.aligned.m8n8.x4.shared.b16 {%0,%1,%2,%3}, [%4];" \
        : "=r"(d0), "=r"(d1), "=r"(d2), "=r"(d3) : "r"(a))

#define LDSM4T(d0, d1, d2, d3, a)                                             \
    asm volatile("ldmatrix.sync.aligned.m8n8.x4.trans.shared.b16 {%0,%1,%2,%3}, [%4];" \
        : "=r"(d0), "=r"(d1), "=r"(d2), "=r"(d3) : "r"(a))

// ---- GEMM tiling: BM=BN=128, BK=64 halves, 2-stage ---------------------------
#define ASTH 72
#define ABYT (128*ASTH*2)
#define STG  (2*ABYT)
#define SMEM_G (2*STG)                 // 73728 B

__device__ __forceinline__ void stage_h64(const __half* P, int ldk,
                                          uint32_t sdst, int r0, int k0, int tid)
{
    #pragma unroll
    for (int i = 0; i < 4; i++) {
        int c = tid + i * 256;
        int row = c >> 3, kc = c & 7;
        CP_ASYNC16(sdst + row * 144 + kc * 16,
                   P + (size_t)(r0 + row) * ldk + k0 + kc * 8);
    }
}

// core mainloop (fragment double-buffering) + epilogue
__device__ __forceinline__ void gemm_core(
    const __half* A, const __half* B, __half* Ch, float* Cf,
    int N, int ldk, int kbase, int T, int m0, int n0)
{
    extern __shared__ char smem[];
    const int tid = threadIdx.x, lane = tid & 31, wid = tid >> 5;
    const int wm = (wid & 3) * 32, wn = (wid >> 2) * 64;
    const int gq = lane >> 2, r = lane & 3;
    const int lrow = lane & 15, lhi = (lane >> 4) * 8;
    const uint32_t sb = smem_u32(smem);
    const uint32_t aoff = ((wm + lrow) * ASTH + lhi) * 2;
    const uint32_t boff = ((wn + lrow) * ASTH + lhi) * 2;

    float cacc[2][8][4];
    #pragma unroll
    for (int i = 0; i < 2; i++)
        #pragma unroll
        for (int j = 0; j < 8; j++)
            #pragma unroll
            for (int q = 0; q < 4; q++) cacc[i][j][q] = 0.0f;

    stage_h64(A, ldk, sb,        m0, kbase, tid);
    stage_h64(B, ldk, sb + ABYT, n0, kbase, tid);
    CP_ASYNC_COMMIT();

    for (int t = 0; t < T; t++) {
        CP_ASYNC_WAIT0();
        __syncthreads();
        if (t + 1 < T) {
            uint32_t base = sb + ((t + 1) & 1) * STG;
            stage_h64(A, ldk, base,        m0, kbase + (t + 1) * 64, tid);
            stage_h64(B, ldk, base + ABYT, n0, kbase + (t + 1) * 64, tid);
            CP_ASYNC_COMMIT();
        }
        const uint32_t bA = sb + (t & 1) * STG;
        const uint32_t bB = bA + ABYT;

        uint32_t fa[2][8], fb[2][16];
        LDSM4(fa[0][0], fa[0][1], fa[0][2], fa[0][3], bA + aoff);
        LDSM4(fa[0][4], fa[0][5], fa[0][6], fa[0][7], bA + aoff + 16*ASTH*2);
        #pragma unroll
        for (int jj = 0; jj < 4; jj++)
            LDSM4(fb[0][4*jj], fb[0][4*jj+1], fb[0][4*jj+2], fb[0][4*jj+3],
                  bB + boff + jj*(16*ASTH*2));

        #pragma unroll
        for (int ks = 0; ks < 4; ks++) {
            const int cur = ks & 1, nxt = cur ^ 1;
            if (ks < 3) {
                LDSM4(fa[nxt][0], fa[nxt][1], fa[nxt][2], fa[nxt][3],
                      bA + aoff + (ks+1)*32);
                LDSM4(fa[nxt][4], fa[nxt][5], fa[nxt][6], fa[nxt][7],
                      bA + aoff + 16*ASTH*2 + (ks+1)*32);
                #pragma unroll
                for (int jj = 0; jj < 4; jj++)
                    LDSM4(fb[nxt][4*jj], fb[nxt][4*jj+1],
                          fb[nxt][4*jj+2], fb[nxt][4*jj+3],
                          bB + boff + jj*(16*ASTH*2) + (ks+1)*32);
            }
            #pragma unroll
            for (int jj = 0; jj < 4; jj++) {
                MMA_F16(cacc[0][2*jj],   fa[cur][0], fa[cur][1], fa[cur][2], fa[cur][3],
                        fb[cur][4*jj],   fb[cur][4*jj+2]);
                MMA_F16(cacc[0][2*jj+1], fa[cur][0], fa[cur][1], fa[cur][2], fa[cur][3],
                        fb[cur][4*jj+1], fb[cur][4*jj+3]);
                MMA_F16(cacc[1][2*jj],   fa[cur][4], fa[cur][5], fa[cur][6], fa[cur][7],
                        fb[cur][4*jj],   fb[cur][4*jj+2]);
                MMA_F16(cacc[1][2*jj+1], fa[cur][4], fa[cur][5], fa[cur][6], fa[cur][7],
                        fb[cur][4*jj+1], fb[cur][4*jj+3]);
            }
        }
    }

    #pragma unroll
    for (int i = 0; i < 2; i++) {
        int row = m0 + wm + i * 16 + gq;
        #pragma unroll
        for (int j = 0; j < 8; j++) {
            int col = n0 + wn + j * 8 + r * 2;
            if (Cf) {
                *(float2*)(Cf + (size_t)row * N + col) =
                    make_float2(cacc[i][j][0], cacc[i][j][1]);
                *(float2*)(Cf + (size_t)(row + 8) * N + col) =
                    make_float2(cacc[i][j][2], cacc[i][j][3]);
            } else {
                *(__half2*)(Ch + (size_t)row * N + col) =
                    __floats2half2_rn(cacc[i][j][0], cacc[i][j][1]);
                *(__half2*)(Ch + (size_t)(row + 8) * N + col) =
                    __floats2half2_rn(cacc[i][j][2], cacc[i][j][3]);
            }
        }
    }
}

// ============================================================================
// MEGA GEMM (single launch, device-side dependency):
//   bid 0..127    : hE/hF = Et/Ft @ hs_th^T (T=64, fp16 out) -> signal g_done
//   bid 128..1151 : q = hs @ Wq^T
//   bid 1152..1279: kp/vp = hE/hF @ Wk/Wv^T  (spin until g_done == 128)
// Safety: EF blocks (lowest bids) are dispatched in wave 1, before any kpvp
// block can be scheduled; spinners (<=128) < concurrent slots (296); q blocks
// always progress => no deadlock.
// ============================================================================
__global__ __launch_bounds__(256, 2) void gemm_mega()
{
    const int bid = blockIdx.x;
    const int tid = threadIdx.x;
    if (bid < 128) {
        int n = bid & 7, m = (bid >> 3) & 1, b = (bid >> 4) & 3, isF = (bid >> 6) & 1;
        const __half* A = isF ? g_Ft_h : g_Et_h;
        const __half* B = g_hs_th + (size_t)b * HIDDEN * QLEN;
        __half* Ch = (isF ? g_hF_h : g_hE_h) + (size_t)b * KP * HIDDEN;
        gemm_core(A, B, Ch, nullptr, HIDDEN, QLEN, 0, 64, m * 128, n * 128);
        __threadfence();
        __syncthreads();
        if (tid == 0) atomicAdd(&g_done, 1);
    } else if (bid < 1152) {
        int s = bid - 128;
        gemm_core(g_hs_h, g_Wq_h, g_q_h, nullptr,
                  HIDDEN, HIDDEN, 0, 16, (s >> 3) * 128, (s & 7) * 128);
    } else {
        int s = bid - 1152;                 // 0..127
        if (tid == 0) {
            while (atomicAdd(&g_done, 0) < 128) { }
        }
        __syncthreads();
        __threadfence();
        int tensor = s >> 6, m = (s >> 3) & 7, n = s & 7;
        const __half* A = tensor ? g_hF_h : g_hE_h;
        const __half* B = tensor ? g_Wv_h : g_Wk_h;
        __half* Ch = tensor ? g_vp_h : g_kp_h;
        gemm_core(A, B, Ch, nullptr, HIDDEN, HIDDEN, 0, 16, m * 128, n * 128);
    }
}

// out-projection GEMM
__global__ __launch_bounds__(256, 2) void gemm_out(float* out)
{
    gemm_core(g_o_h, g_Wo_h, nullptr, out, HIDDEN, HIDDEN, 0, 16,
              blockIdx.y * 128, blockIdx.x * 128);
}

// ============================================================================
// fp16 mma attention: scores fp32-acc, PV fp32-acc, register P, h2exp2,
// pipelined K-fragments, ldmatrix.trans for V. (R14-proven.)
// ============================================================================
#define QST 72
#define KST 72
#define VST 72
#define QSO 0
#define KSO (128*QST)
#define VSO (KSO + 256*KST)
#define ATTN_SMEM ((VSO + 256*VST) * 2) // 92160 B

__global__ __launch_bounds__(256, 2) void attn_h()
{
    extern __shared__ __half smh[];

    const int tid  = threadIdx.x;
    const int lane = tid & 31;
    const int wid  = tid >> 5;
    const int gq   = lane >> 2, r = lane & 3;
    const int lrow = lane & 15, lhi = (lane >> 4) * 8;
    const int q0   = blockIdx.x << 7;
    const int h    = blockIdx.y;
    const int b    = blockIdx.z;

    const __half* qb  = g_q_h  + ((size_t)b*QLEN + q0) * HIDDEN + h*HD;
    const __half* kpb = g_kp_h + (size_t)b*KP*HIDDEN + h*HD;
    const __half* vpb = g_vp_h + (size_t)b*KP*HIDDEN + h*HD;
    const uint32_t sb = smem_u32(smh);

    #pragma unroll
    for (int i = 0; i < 4; i++) {
        int c = tid + i * 256;
        int row = c >> 3, kc = c & 7;
        CP_ASYNC16(sb + (QSO + row * QST) * 2 + kc * 16,
                   qb + (size_t)row * HIDDEN + kc * 8);
    }
    #pragma unroll
    for (int i = 0; i < 8; i++) {
        int c = tid + i * 256;
        int row = c >> 3, kc = c & 7;
        CP_ASYNC16(sb + (KSO + row * KST) * 2 + kc * 16,
                   kpb + (size_t)row * HIDDEN + kc * 8);
    }
    CP_ASYNC_COMMIT();
    #pragma unroll
    for (int i = 0; i < 8; i++) {
        int c = tid + i * 256;
        int row = c >> 3, kc = c & 7;
        CP_ASYNC16(sb + (VSO + row * VST) * 2 + kc * 16,
                   vpb + (size_t)row * HIDDEN + kc * 8);
    }
    CP_ASYNC_COMMIT();

    CP_ASYNC_WAIT1();
    __syncthreads();

    const int wm = wid * 16;
    const uint32_t qaoff = sb + ((QSO + (wm + lrow) * QST + lhi) * 2);
    uint32_t QA[4][4];
    #pragma unroll
    for (int ks = 0; ks < 4; ks++)
        LDSM4(QA[ks][0], QA[ks][1], QA[ks][2], QA[ks][3], qaoff + ks * 32);

    const float KSC = 0.18033688f;
    const uint32_t kboff = sb + ((KSO + lrow * KST + lhi) * 2);
    uint32_t P[64];
    float sum0 = 0.0f, sum1 = 0.0f;

    uint32_t rbuf[2][4];
    LDSM4(rbuf[0][0], rbuf[0][1], rbuf[0][2], rbuf[0][3], kboff);

    #pragma unroll
    for (int jp = 0; jp < 16; jp++) {
        float c0[4] = {0.f, 0.f, 0.f, 0.f};
        float c1[4] = {0.f, 0.f, 0.f, 0.f};
        #pragma unroll
        for (int ks = 0; ks < 4; ks++) {
            const int f = jp * 4 + ks;
            const int cur = f & 1, nxt = cur ^ 1;
            if (f < 63) {
                const int fn = f + 1;
                LDSM4(rbuf[nxt][0], rbuf[nxt][1], rbuf[nxt][2], rbuf[nxt][3],
                      kboff + (fn >> 2) * (16*KST*2) + (fn & 3) * 32);
            }
            MMA_F16(c0, QA[ks][0], QA[ks][1], QA[ks][2], QA[ks][3],
                    rbuf[cur][0], rbuf[cur][2]);
            MMA_F16(c1, QA[ks][0], QA[ks][1], QA[ks][2], QA[ks][3],
                    rbuf[cur][1], rbuf[cur][3]);
        }
        __half2 eA = h2exp2(__floats2half2_rn(c0[0]*KSC, c0[1]*KSC));
        __half2 eB = h2exp2(__floats2half2_rn(c0[2]*KSC, c0[3]*KSC));
        __half2 eC = h2exp2(__floats2half2_rn(c1[0]*KSC, c1[1]*KSC));
        __half2 eD = h2exp2(__floats2half2_rn(c1[2]*KSC, c1[3]*KSC));
        P[4*jp + 0] = *(uint32_t*)&eA;
        P[4*jp + 1] = *(uint32_t*)&eB;
        P[4*jp + 2] = *(uint32_t*)&eC;
        P[4*jp + 3] = *(uint32_t*)&eD;
        __half2 t0 = __hadd2(eA, eC);
        __half2 t1 = __hadd2(eB, eD);
        float2 f0 = __half22float2(t0); sum0 += f0.x + f0.y;
        float2 f1 = __half22float2(t1); sum1 += f1.x + f1.y;
    }

    sum0 += __shfl_xor_sync(0xffffffffu, sum0, 1);
    sum0 += __shfl_xor_sync(0xffffffffu, sum0, 2);
    sum1 += __shfl_xor_sync(0xffffffffu, sum1, 1);
    sum1 += __shfl_xor_sync(0xffffffffu, sum1, 2);
    const float ri0 = 1.0f / sum0, ri1 = 1.0f / sum1;

    CP_ASYNC_WAIT0();
    __syncthreads();

    float c2[8][4];
    #pragma unroll
    for (int j = 0; j < 8; j++)
        #pragma unroll
        for (int q = 0; q < 4; q++) c2[j][q] = 0.0f;

    #pragma unroll
    for (int t = 0; t < 16; t++) {
        #pragma unroll
        for (int g = 0; g < 4; g++) {
            uint32_t rb[4];
            LDSM4T(rb[0], rb[1], rb[2], rb[3],
                   sb + ((VSO + (t*16 + lrow) * VST + g*16 + lhi) * 2));
            MMA_F16(c2[2*g],   P[4*t+0], P[4*t+1], P[4*t+2], P[4*t+3], rb[0], rb[1]);
            MMA_F16(c2[2*g+1], P[4*t+0], P[4*t+1], P[4*t+2], P[4*t+3], rb[2], rb[3]);
        }
    }

    __half* ob = g_o_h + ((size_t)b*QLEN + q0 + wm) * HIDDEN + h*HD;
    #pragma unroll
    for (int j = 0; j < 8; j++) {
        int col = j * 8 + r * 2;
        *(__half2*)(ob + (size_t)gq * HIDDEN + col) =
            __floats2half2_rn(c2[j][0] * ri0, c2[j][1] * ri0);
        *(__half2*)(ob + (size_t)(gq + 8) * HIDDEN + col) =
            __floats2half2_rn(c2[j][2] * ri1, c2[j][3] * ri1);
    }
}

// ============================================================================
// Unified pre-pass (also resets g_done)
// ============================================================================
__global__ void prep(const float* __restrict__ hs,
                     const float* __restrict__ w0, const float* __restrict__ w1,
                     const float* __restrict__ w2, const float* __restrict__ w3,
                     const float* __restrict__ E,  const float* __restrict__ F)
{
    __shared__ float t[64][65];
    const int bid = blockIdx.x;
    const int tx = threadIdx.x, ty = threadIdx.y;

    if (bid == 0 && tx == 0 && ty == 0) g_done = 0;

    if (bid < 4096) {               // ---- conv_hs: 64(s) x 64(n) tiles ------
        int x = bid & 63, y = (bid >> 6) & 15, b = bid >> 10;
        int s0 = x * 64, n0 = y * 64;
        #pragma unroll
        for (int i = 0; i < 8; i++) {
            int s = s0 + ty + i * 8;
            const float* src = hs + ((size_t)b * QLEN + s) * HIDDEN + n0;
            t[ty + i * 8][tx]      = src[tx];
            t[ty + i * 8][tx + 32] = src[tx + 32];
        }
        __syncthreads();
        #pragma unroll
        for (int i = 0; i < 8; i++) {
            int row = ty + i * 8;
            __half2 hv = __floats2half2_rn(t[row][2*tx], t[row][2*tx + 1]);
            *(__half2*)&g_hs_h[((size_t)b * QLEN + s0 + row) * HIDDEN + n0 + 2*tx] = hv;
        }
        #pragma unroll
        for (int i = 0; i < 8; i++) {
            int n = ty + i * 8;
            __half2 hv = __floats2half2_rn(t[2*tx][n], t[2*tx + 1][n]);
            *(__half2*)&g_hs_th[((size_t)b * HIDDEN + n0 + n) * QLEN + s0 + 2*tx] = hv;
        }
    } else if (bid < 8192) {        // ---- conv_w4 ---------------------------
        int s = bid - 4096;
        int mat = s >> 10;
        const float* src = (mat == 0) ? w0 : (mat == 1) ? w1 : (mat == 2) ? w2 : w3;
        __half* dst = (mat == 0) ? g_Wq_h : (mat == 1) ? g_Wk_h
                    : (mat == 2) ? g_Wv_h : g_Wo_h;
        int i = (s & 1023) * 256 + ty * 32 + tx;
        float4 v = ((const float4*)src)[i];
        ((__half2*)dst)[i*2]   = __floats2half2_rn(v.x, v.y);
        ((__half2*)dst)[i*2+1] = __floats2half2_rn(v.z, v.w);
    } else {                        // ---- transpose_efh ---------------------
        int s = bid - 8192;
        int z = s >> 9, rem = s & 511;
        int x = rem & 63, y = rem >> 6;
        const float* src = z ? F : E;
        __half* dst = z ? g_Ft_h : g_Et_h;
        int s0 = x * 64, m0 = y * 32;
        #pragma unroll
        for (int i = 0; i < 8; i++)
            t[ty + i * 8][tx] = src[(size_t)(s0 + ty + i * 8) * KP + m0 + tx];
        __syncthreads();
        #pragma unroll
        for (int i = 0; i < 4; i++) {
            int m = m0 + ty + i * 8;
            __half2 hv = __floats2half2_rn(t[2*tx][ty + i * 8], t[2*tx + 1][ty + i * 8]);
            *(__half2*)&dst[(size_t)m * QLEN + s0 + 2*tx] = hv;
        }
    }
}

// ---------------------------------------------------------------------------
extern "C" void kernel_launch(void* const* d_in, const int* in_sizes, int n_in,
                              void* d_out, int out_size)
{
    const float* hs = (const float*)d_in[0];
    const float* Wq = (const float*)d_in[1];
    const float* Wk = (const float*)d_in[2];
    const float* Wv = (const float*)d_in[3];
    const float* Wo = (const float*)d_in[4];
    const float* E  = (const float*)d_in[5];
    const float* F  = (const float*)d_in[6];
    float* out = (float*)d_out;

    cudaFuncSetAttribute(gemm_mega, cudaFuncAttributeMaxDynamicSharedMemorySize, SMEM_G);
    cudaFuncSetAttribute(gemm_out,  cudaFuncAttributeMaxDynamicSharedMemorySize, SMEM_G);
    cudaFuncSetAttribute(attn_h,    cudaFuncAttributeMaxDynamicSharedMemorySize, ATTN_SMEM);

    dim3 blk(256);

    // unified pre-pass (also resets g_done)
    prep<<<9216, dim3(32, 8)>>>(hs, Wq, Wk, Wv, Wo, E, F);

    // single fused launch: hE/hF + q-projection + kp/vp (device-side dep)
    gemm_mega<<<1280, blk, SMEM_G>>>();

    // attention
    attn_h<<<dim3(QLEN/128, HEADS, BSZ), blk, ATTN_SMEM>>>();

    // out = o @ Wo^T (fp32 to d_out)
    gemm_out<<<dim3(8, 128), blk, SMEM_G>>>(out);
}

// round 16
// speedup vs baseline: 1.0865x; 1.0051x over previous
#include <cuda_runtime.h>
#include <cuda_fp16.h>
#include <cstdint>

#define HIDDEN 1024
#define HEADS  16
#define HD     64
#define KP     256
#define BSZ    4
#define QLEN   4096
#define MR     (BSZ*QLEN)   // 16384

// ---------------- scratch (device globals) ----------------------------------
__device__ __half g_hs_h [MR*HIDDEN];
__device__ __half g_hs_th[(size_t)BSZ*HIDDEN*QLEN];
__device__ __half g_q_h  [MR*HIDDEN];
__device__ __half g_o_h  [MR*HIDDEN];
__device__ __half g_kp_h [BSZ*KP*HIDDEN];
__device__ __half g_vp_h [BSZ*KP*HIDDEN];
__device__ __half g_hE_h [BSZ*KP*HIDDEN];
__device__ __half g_hF_h [BSZ*KP*HIDDEN];
__device__ __half g_Et_h [KP*QLEN];
__device__ __half g_Ft_h [KP*QLEN];
__device__ __half g_Wq_h [HIDDEN*HIDDEN];
__device__ __half g_Wk_h [HIDDEN*HIDDEN];
__device__ __half g_Wv_h [HIDDEN*HIDDEN];
__device__ __half g_Wo_h [HIDDEN*HIDDEN];

// dependency flags (reset in prep)
__device__ int g_ef_done;        // counts to 128
__device__ int g_qf  [1024];     // q tile (m 0..127, n 0..7): [m*8+n]
__device__ int g_kpf [64];       // kp tile (m 0..7, n 0..7)
__device__ int g_vpf [64];
__device__ int g_att [128];      // per (b*32+qtile), counts to 16

// ============================== helpers =====================================
#define CP_ASYNC16(s, g) \
    asm volatile("cp.async.cg.shared.global [%0], [%1], 16;" :: "r"(s), "l"(g))
#define CP_ASYNC_COMMIT() asm volatile("cp.async.commit_group;")
#define CP_ASYNC_WAIT1()  asm volatile("cp.async.wait_group 1;" ::: "memory")
#define CP_ASYNC_WAIT0()  asm volatile("cp.async.wait_group 0;" ::: "memory")

__device__ __forceinline__ uint32_t smem_u32(const void* p) {
    uint32_t a;
    asm("{ .reg .u64 t; cvta.to.shared.u64 t, %1; cvt.u32.u64 %0, t; }"
        : "=r"(a) : "l"(p));
    return a;
}

#define MMA_F16(c, a0, a1, a2, a3, b0, b1)                                    \
    asm volatile("mma.sync.aligned.m16n8k16.row.col.f32.f16.f16.f32 "         \
        "{%0,%1,%2,%3}, {%4,%5,%6,%7}, {%8,%9}, {%0,%1,%2,%3};"               \
        : "+f"((c)[0]), "+f"((c)[1]), "+f"((c)[2]), "+f"((c)[3])              \
        : "r"(a0), "r"(a1), "r"(a2), "r"(a3), "r"(b0), "r"(b1))

#define LDSM4(d0, d1, d2, d3, a)                                              \
    asm volatile("ldmatrix.sync.aligned.m8n8.x4.shared.b16 {%0,%1,%2,%3}, [%4];" \
        : "=r"(d0), "=r"(d1), "=r"(d2), "=r"(d3) : "r"(a))

#define LDSM4T(d0, d1, d2, d3, a)                                             \
    asm volatile("ldmatrix.sync.aligned.m8n8.x4.trans.shared.b16 {%0,%1,%2,%3}, [%4];" \
        : "=r"(d0), "=r"(d1), "=r"(d2), "=r"(d3) : "r"(a))

__device__ __forceinline__ void spin_on(int* flag) {
    while (atomicAdd(flag, 0) == 0) { }
}
__device__ __forceinline__ void mark(int* flag) {
    __threadfence();
    atomicExch(flag, 1);
}

// ---- GEMM tiling: BM=BN=128, BK=64 halves, 2-stage ---------------------------
#define ASTH 72
#define ABYT (128*ASTH*2)
#define STG  (2*ABYT)

__device__ __forceinline__ void stage_h64(const __half* P, int ldk,
                                          uint32_t sdst, int r0, int k0, int tid)
{
    #pragma unroll
    for (int i = 0; i < 4; i++) {
        int c = tid + i * 256;
        int row = c >> 3, kc = c & 7;
        CP_ASYNC16(sdst + row * 144 + kc * 16,
                   P + (size_t)(r0 + row) * ldk + k0 + kc * 8);
    }
}

// core mainloop (fragment double-buffering) + epilogue
__device__ __forceinline__ void gemm_core(
    const __half* A, const __half* B, __half* Ch, float* Cf,
    int N, int ldk, int kbase, int T, int m0, int n0)
{
    extern __shared__ char smem[];
    const int tid = threadIdx.x, lane = tid & 31, wid = tid >> 5;
    const int wm = (wid & 3) * 32, wn = (wid >> 2) * 64;
    const int gq = lane >> 2, r = lane & 3;
    const int lrow = lane & 15, lhi = (lane >> 4) * 8;
    const uint32_t sb = smem_u32(smem);
    const uint32_t aoff = ((wm + lrow) * ASTH + lhi) * 2;
    const uint32_t boff = ((wn + lrow) * ASTH + lhi) * 2;

    float cacc[2][8][4];
    #pragma unroll
    for (int i = 0; i < 2; i++)
        #pragma unroll
        for (int j = 0; j < 8; j++)
            #pragma unroll
            for (int q = 0; q < 4; q++) cacc[i][j][q] = 0.0f;

    stage_h64(A, ldk, sb,        m0, kbase, tid);
    stage_h64(B, ldk, sb + ABYT, n0, kbase, tid);
    CP_ASYNC_COMMIT();

    for (int t = 0; t < T; t++) {
        CP_ASYNC_WAIT0();
        __syncthreads();
        if (t + 1 < T) {
            uint32_t base = sb + ((t + 1) & 1) * STG;
            stage_h64(A, ldk, base,        m0, kbase + (t + 1) * 64, tid);
            stage_h64(B, ldk, base + ABYT, n0, kbase + (t + 1) * 64, tid);
            CP_ASYNC_COMMIT();
        }
        const uint32_t bA = sb + (t & 1) * STG;
        const uint32_t bB = bA + ABYT;

        uint32_t fa[2][8], fb[2][16];
        LDSM4(fa[0][0], fa[0][1], fa[0][2], fa[0][3], bA + aoff);
        LDSM4(fa[0][4], fa[0][5], fa[0][6], fa[0][7], bA + aoff + 16*ASTH*2);
        #pragma unroll
        for (int jj = 0; jj < 4; jj++)
            LDSM4(fb[0][4*jj], fb[0][4*jj+1], fb[0][4*jj+2], fb[0][4*jj+3],
                  bB + boff + jj*(16*ASTH*2));

        #pragma unroll
        for (int ks = 0; ks < 4; ks++) {
            const int cur = ks & 1, nxt = cur ^ 1;
            if (ks < 3) {
                LDSM4(fa[nxt][0], fa[nxt][1], fa[nxt][2], fa[nxt][3],
                      bA + aoff + (ks+1)*32);
                LDSM4(fa[nxt][4], fa[nxt][5], fa[nxt][6], fa[nxt][7],
                      bA + aoff + 16*ASTH*2 + (ks+1)*32);
                #pragma unroll
                for (int jj = 0; jj < 4; jj++)
                    LDSM4(fb[nxt][4*jj], fb[nxt][4*jj+1],
                          fb[nxt][4*jj+2], fb[nxt][4*jj+3],
                          bB + boff + jj*(16*ASTH*2) + (ks+1)*32);
            }
            #pragma unroll
            for (int jj = 0; jj < 4; jj++) {
                MMA_F16(cacc[0][2*jj],   fa[cur][0], fa[cur][1], fa[cur][2], fa[cur][3],
                        fb[cur][4*jj],   fb[cur][4*jj+2]);
                MMA_F16(cacc[0][2*jj+1], fa[cur][0], fa[cur][1], fa[cur][2], fa[cur][3],
                        fb[cur][4*jj+1], fb[cur][4*jj+3]);
                MMA_F16(cacc[1][2*jj],   fa[cur][4], fa[cur][5], fa[cur][6], fa[cur][7],
                        fb[cur][4*jj],   fb[cur][4*jj+2]);
                MMA_F16(cacc[1][2*jj+1], fa[cur][4], fa[cur][5], fa[cur][6], fa[cur][7],
                        fb[cur][4*jj+1], fb[cur][4*jj+3]);
            }
        }
    }

    #pragma unroll
    for (int i = 0; i < 2; i++) {
        int row = m0 + wm + i * 16 + gq;
        #pragma unroll
        for (int j = 0; j < 8; j++) {
            int col = n0 + wn + j * 8 + r * 2;
            if (Cf) {
                *(float2*)(Cf + (size_t)row * N + col) =
                    make_float2(cacc[i][j][0], cacc[i][j][1]);
                *(float2*)(Cf + (size_t)(row + 8) * N + col) =
                    make_float2(cacc[i][j][2], cacc[i][j][3]);
            } else {
                *(__half2*)(Ch + (size_t)row * N + col) =
                    __floats2half2_rn(cacc[i][j][0], cacc[i][j][1]);
                *(__half2*)(Ch + (size_t)(row + 8) * N + col) =
                    __floats2half2_rn(cacc[i][j][2], cacc[i][j][3]);
            }
        }
    }
}

// ---- attention body (R14-proven) ---------------------------------------------
#define QST 72
#define KST 72
#define VST 72
#define QSO 0
#define KSO (128*QST)
#define VSO (KSO + 256*KST)
#define ATTN_SMEM ((VSO + 256*VST) * 2) // 92160 B

__device__ __forceinline__ void attn_body(int qtile, int h, int b)
{
    extern __shared__ char smem[];
    __half* smh = (__half*)smem;

    const int tid  = threadIdx.x;
    const int lane = tid & 31;
    const int wid  = tid >> 5;
    const int gq   = lane >> 2, r = lane & 3;
    const int lrow = lane & 15, lhi = (lane >> 4) * 8;
    const int q0   = qtile << 7;

    const __half* qb  = g_q_h  + ((size_t)b*QLEN + q0) * HIDDEN + h*HD;
    const __half* kpb = g_kp_h + (size_t)b*KP*HIDDEN + h*HD;
    const __half* vpb = g_vp_h + (size_t)b*KP*HIDDEN + h*HD;
    const uint32_t sb = smem_u32(smh);

    #pragma unroll
    for (int i = 0; i < 4; i++) {
        int c = tid + i * 256;
        int row = c >> 3, kc = c & 7;
        CP_ASYNC16(sb + (QSO + row * QST) * 2 + kc * 16,
                   qb + (size_t)row * HIDDEN + kc * 8);
    }
    #pragma unroll
    for (int i = 0; i < 8; i++) {
        int c = tid + i * 256;
        int row = c >> 3, kc = c & 7;
        CP_ASYNC16(sb + (KSO + row * KST) * 2 + kc * 16,
                   kpb + (size_t)row * HIDDEN + kc * 8);
    }
    CP_ASYNC_COMMIT();
    #pragma unroll
    for (int i = 0; i < 8; i++) {
        int c = tid + i * 256;
        int row = c >> 3, kc = c & 7;
        CP_ASYNC16(sb + (VSO + row * VST) * 2 + kc * 16,
                   vpb + (size_t)row * HIDDEN + kc * 8);
    }
    CP_ASYNC_COMMIT();

    CP_ASYNC_WAIT1();
    __syncthreads();

    const int wm = wid * 16;
    const uint32_t qaoff = sb + ((QSO + (wm + lrow) * QST + lhi) * 2);
    uint32_t QA[4][4];
    #pragma unroll
    for (int ks = 0; ks < 4; ks++)
        LDSM4(QA[ks][0], QA[ks][1], QA[ks][2], QA[ks][3], qaoff + ks * 32);

    const float KSC = 0.18033688f;
    const uint32_t kboff = sb + ((KSO + lrow * KST + lhi) * 2);
    uint32_t P[64];
    float sum0 = 0.0f, sum1 = 0.0f;

    uint32_t rbuf[2][4];
    LDSM4(rbuf[0][0], rbuf[0][1], rbuf[0][2], rbuf[0][3], kboff);

    #pragma unroll
    for (int jp = 0; jp < 16; jp++) {
        float c0[4] = {0.f, 0.f, 0.f, 0.f};
        float c1[4] = {0.f, 0.f, 0.f, 0.f};
        #pragma unroll
        for (int ks = 0; ks < 4; ks++) {
            const int f = jp * 4 + ks;
            const int cur = f & 1, nxt = cur ^ 1;
            if (f < 63) {
                const int fn = f + 1;
                LDSM4(rbuf[nxt][0], rbuf[nxt][1], rbuf[nxt][2], rbuf[nxt][3],
                      kboff + (fn >> 2) * (16*KST*2) + (fn & 3) * 32);
            }
            MMA_F16(c0, QA[ks][0], QA[ks][1], QA[ks][2], QA[ks][3],
                    rbuf[cur][0], rbuf[cur][2]);
            MMA_F16(c1, QA[ks][0], QA[ks][1], QA[ks][2], QA[ks][3],
                    rbuf[cur][1], rbuf[cur][3]);
        }
        __half2 eA = h2exp2(__floats2half2_rn(c0[0]*KSC, c0[1]*KSC));
        __half2 eB = h2exp2(__floats2half2_rn(c0[2]*KSC, c0[3]*KSC));
        __half2 eC = h2exp2(__floats2half2_rn(c1[0]*KSC, c1[1]*KSC));
        __half2 eD = h2exp2(__floats2half2_rn(c1[2]*KSC, c1[3]*KSC));
        P[4*jp + 0] = *(uint32_t*)&eA;
        P[4*jp + 1] = *(uint32_t*)&eB;
        P[4*jp + 2] = *(uint32_t*)&eC;
        P[4*jp + 3] = *(uint32_t*)&eD;
        __half2 t0 = __hadd2(eA, eC);
        __half2 t1 = __hadd2(eB, eD);
        float2 f0 = __half22float2(t0); sum0 += f0.x + f0.y;
        float2 f1 = __half22float2(t1); sum1 += f1.x + f1.y;
    }

    sum0 += __shfl_xor_sync(0xffffffffu, sum0, 1);
    sum0 += __shfl_xor_sync(0xffffffffu, sum0, 2);
    sum1 += __shfl_xor_sync(0xffffffffu, sum1, 1);
    sum1 += __shfl_xor_sync(0xffffffffu, sum1, 2);
    const float ri0 = 1.0f / sum0, ri1 = 1.0f / sum1;

    CP_ASYNC_WAIT0();
    __syncthreads();

    float c2[8][4];
    #pragma unroll
    for (int j = 0; j < 8; j++)
        #pragma unroll
        for (int q = 0; q < 4; q++) c2[j][q] = 0.0f;

    #pragma unroll
    for (int t = 0; t < 16; t++) {
        #pragma unroll
        for (int g = 0; g < 4; g++) {
            uint32_t rb[4];
            LDSM4T(rb[0], rb[1], rb[2], rb[3],
                   sb + ((VSO + (t*16 + lrow) * VST + g*16 + lhi) * 2));
            MMA_F16(c2[2*g],   P[4*t+0], P[4*t+1], P[4*t+2], P[4*t+3], rb[0], rb[1]);
            MMA_F16(c2[2*g+1], P[4*t+0], P[4*t+1], P[4*t+2], P[4*t+3], rb[2], rb[3]);
        }
    }

    __half* ob = g_o_h + ((size_t)b*QLEN + q0 + wm) * HIDDEN + h*HD;
    #pragma unroll
    for (int j = 0; j < 8; j++) {
        int col = j * 8 + r * 2;
        *(__half2*)(ob + (size_t)gq * HIDDEN + col) =
            __floats2half2_rn(c2[j][0] * ri0, c2[j][1] * ri0);
        *(__half2*)(ob + (size_t)(gq + 8) * HIDDEN + col) =
            __floats2half2_rn(c2[j][2] * ri1, c2[j][3] * ri1);
    }
}

// ============================================================================
// ONE fused launch, 4352 blocks, fine-grained device-side dependencies:
//   bid 0..127    : hE/hF (T=64)                -> g_ef_done++
//   bid 128..1151 : q = hs @ Wq^T               -> g_qf[tile] = 1
//   bid 1152..1279: kp/vp (spin g_ef_done==128) -> g_kpf/g_vpf[tile] = 1
//   bid 1280..3327: attention (spin 1 q + 2 kp + 2 vp flags) -> g_att[y]++
//   bid 3328..4351: out-proj (spin g_att[y]==16)
// Safety: bid-ordered dispatch => every producer block is resident before any
// of its consumers spins; spinners never block producer progress.
// ============================================================================
__global__ __launch_bounds__(256, 2) void fused_all(float* out)
{
    const int bid = blockIdx.x;
    const int tid = threadIdx.x;

    if (bid < 128) {
        int n = bid & 7, m = (bid >> 3) & 1, b = (bid >> 4) & 3, isF = (bid >> 6) & 1;
        const __half* A = isF ? g_Ft_h : g_Et_h;
        const __half* B = g_hs_th + (size_t)b * HIDDEN * QLEN;
        __half* Ch = (isF ? g_hF_h : g_hE_h) + (size_t)b * KP * HIDDEN;
        gemm_core(A, B, Ch, nullptr, HIDDEN, QLEN, 0, 64, m * 128, n * 128);
        __threadfence();
        __syncthreads();
        if (tid == 0) atomicAdd(&g_ef_done, 1);
    } else if (bid < 1152) {
        int s = bid - 128;
        gemm_core(g_hs_h, g_Wq_h, g_q_h, nullptr,
                  HIDDEN, HIDDEN, 0, 16, (s >> 3) * 128, (s & 7) * 128);
        __syncthreads();
        if (tid == 0) mark(&g_qf[s]);
    } else if (bid < 1280) {
        int s = bid - 1152;                 // 0..127
        if (tid == 0) {
            while (atomicAdd(&g_ef_done, 0) < 128) { }
        }
        __syncthreads();
        __threadfence();
        int tensor = s >> 6, m = (s >> 3) & 7, n = s & 7;
        const __half* A = tensor ? g_hF_h : g_hE_h;
        const __half* B = tensor ? g_Wv_h : g_Wk_h;
        __half* Ch = tensor ? g_vp_h : g_kp_h;
        gemm_core(A, B, Ch, nullptr, HIDDEN, HIDDEN, 0, 16, m * 128, n * 128);
        __syncthreads();
        if (tid == 0) mark((tensor ? g_vpf : g_kpf) + s % 64);
    } else if (bid < 3328) {
        int s = bid - 1280;                 // 0..2047
        int qtile = s & 31, h = (s >> 5) & 15, b = s >> 9;
        int nt = h >> 1;
        if (tid == 0) {
            spin_on(&g_qf[(b * 32 + qtile) * 8 + nt]);
            spin_on(&g_kpf[(2 * b)     * 8 + nt]);
            spin_on(&g_kpf[(2 * b + 1) * 8 + nt]);
            spin_on(&g_vpf[(2 * b)     * 8 + nt]);
            spin_on(&g_vpf[(2 * b + 1) * 8 + nt]);
        }
        __syncthreads();
        __threadfence();
        attn_body(qtile, h, b);
        __threadfence();
        __syncthreads();
        if (tid == 0) atomicAdd(&g_att[b * 32 + qtile], 1);
    } else {
        int s = bid - 3328;                 // 0..1023
        int n = s & 7, y = s >> 3;          // y = row tile 0..127
        if (tid == 0) {
            while (atomicAdd(&g_att[y], 0) < 16) { }
        }
        __syncthreads();
        __threadfence();
        gemm_core(g_o_h, g_Wo_h, nullptr, out,
                  HIDDEN, HIDDEN, 0, 16, y * 128, n * 128);
    }
}

// ============================================================================
// Unified pre-pass (block 0 also resets all dependency flags)
// ============================================================================
__global__ void prep(const float* __restrict__ hs,
                     const float* __restrict__ w0, const float* __restrict__ w1,
                     const float* __restrict__ w2, const float* __restrict__ w3,
                     const float* __restrict__ E,  const float* __restrict__ F)
{
    __shared__ float t[64][65];
    const int bid = blockIdx.x;
    const int tx = threadIdx.x, ty = threadIdx.y;
    const int ltid = ty * 32 + tx;

    if (bid == 0) {                 // reset flags (1281 ints, 256 threads)
        if (ltid == 0) g_ef_done = 0;
        for (int i = ltid; i < 1024; i += 256) g_qf[i] = 0;
        if (ltid < 64)  g_kpf[ltid] = 0;
        if (ltid < 64)  g_vpf[ltid] = 0;
        if (ltid < 128) g_att[ltid] = 0;
    }

    if (bid < 4096) {               // ---- conv_hs: 64(s) x 64(n) tiles ------
        int x = bid & 63, y = (bid >> 6) & 15, b = bid >> 10;
        int s0 = x * 64, n0 = y * 64;
        #pragma unroll
        for (int i = 0; i < 8; i++) {
            int s = s0 + ty + i * 8;
            const float* src = hs + ((size_t)b * QLEN + s) * HIDDEN + n0;
            t[ty + i * 8][tx]      = src[tx];
            t[ty + i * 8][tx + 32] = src[tx + 32];
        }
        __syncthreads();
        #pragma unroll
        for (int i = 0; i < 8; i++) {
            int row = ty + i * 8;
            __half2 hv = __floats2half2_rn(t[row][2*tx], t[row][2*tx + 1]);
            *(__half2*)&g_hs_h[((size_t)b * QLEN + s0 + row) * HIDDEN + n0 + 2*tx] = hv;
        }
        #pragma unroll
        for (int i = 0; i < 8; i++) {
            int n = ty + i * 8;
            __half2 hv = __floats2half2_rn(t[2*tx][n], t[2*tx + 1][n]);
            *(__half2*)&g_hs_th[((size_t)b * HIDDEN + n0 + n) * QLEN + s0 + 2*tx] = hv;
        }
    } else if (bid < 8192) {        // ---- conv_w4 ---------------------------
        int s = bid - 4096;
        int mat = s >> 10;
        const float* src = (mat == 0) ? w0 : (mat == 1) ? w1 : (mat == 2) ? w2 : w3;
        __half* dst = (mat == 0) ? g_Wq_h : (mat == 1) ? g_Wk_h
                    : (mat == 2) ? g_Wv_h : g_Wo_h;
        int i = (s & 1023) * 256 + ltid;
        float4 v = ((const float4*)src)[i];
        ((__half2*)dst)[i*2]   = __floats2half2_rn(v.x, v.y);
        ((__half2*)dst)[i*2+1] = __floats2half2_rn(v.z, v.w);
    } else {                        // ---- transpose_efh ---------------------
        int s = bid - 8192;
        int z = s >> 9, rem = s & 511;
        int x = rem & 63, y = rem >> 6;
        const float* src = z ? F : E;
        __half* dst = z ? g_Ft_h : g_Et_h;
        int s0 = x * 64, m0 = y * 32;
        #pragma unroll
        for (int i = 0; i < 8; i++)
            t[ty + i * 8][tx] = src[(size_t)(s0 + ty + i * 8) * KP + m0 + tx];
        __syncthreads();
        #pragma unroll
        for (int i = 0; i < 4; i++) {
            int m = m0 + ty + i * 8;
            __half2 hv = __floats2half2_rn(t[2*tx][ty + i * 8], t[2*tx + 1][ty + i * 8]);
            *(__half2*)&dst[(size_t)m * QLEN + s0 + 2*tx] = hv;
        }
    }
}

// ---------------------------------------------------------------------------
extern "C" void kernel_launch(void* const* d_in, const int* in_sizes, int n_in,
                              void* d_out, int out_size)
{
    const float* hs = (const float*)d_in[0];
    const float* Wq = (const float*)d_in[1];
    const float* Wk = (const float*)d_in[2];
    const float* Wv = (const float*)d_in[3];
    const float* Wo = (const float*)d_in[4];
    const float* E  = (const float*)d_in[5];
    const float* F  = (const float*)d_in[6];
    float* out = (float*)d_out;

    cudaFuncSetAttribute(fused_all, cudaFuncAttributeMaxDynamicSharedMemorySize,
                         ATTN_SMEM);

    // unified pre-pass (also resets dependency flags)
    prep<<<9216, dim3(32, 8)>>>(hs, Wq, Wk, Wv, Wo, E, F);

    // everything else: one launch with device-side dependencies
    fused_all<<<4352, 256, ATTN_SMEM>>>(out);
}